// round 1
// baseline (speedup 1.0000x reference)
#include <cuda_runtime.h>
#include <math.h>

#define NB   2
#define SEQ  4096
#define EMB  512
#define NH   8
#define HD   64
#define NROWS (NB*SEQ)   // 8192

// Scratch (allocation-free): [B,H,S,D] layouts, 16 MB each.
__device__ float g_Q[NB*NH*SEQ*HD];
__device__ float g_K[NB*NH*SEQ*HD];
__device__ float g_V[NB*NH*SEQ*HD];
__device__ float g_O[NB*NH*SEQ*HD];

// ---------------------------------------------------------------------------
// Kernel 1: QKV projection. Y = X @ W^T + b, scattered into [B,H,S,D].
// 128x128 tile, BK=8, 256 threads, 8x8 per-thread register blocking.
// grid = (NROWS/128, EMB/128, 3)  (z selects q/k/v)
// ---------------------------------------------------------------------------
__global__ __launch_bounds__(256) void proj_qkv_kernel(
    const float* __restrict__ x,
    const float* __restrict__ Wq, const float* __restrict__ bq,
    const float* __restrict__ Wk, const float* __restrict__ bk,
    const float* __restrict__ Wv, const float* __restrict__ bv)
{
    __shared__ float As[8][128];
    __shared__ float Bs[8][128];

    const float* W; const float* bias; float* outp;
    if (blockIdx.z == 0)      { W = Wq; bias = bq; outp = g_Q; }
    else if (blockIdx.z == 1) { W = Wk; bias = bk; outp = g_K; }
    else                      { W = Wv; bias = bv; outp = g_V; }

    const int t   = threadIdx.x;
    const int tr  = t >> 4;          // 0..15
    const int tc  = t & 15;          // 0..15
    const int bm0 = blockIdx.x * 128;
    const int bn0 = blockIdx.y * 128;
    const int lrow = t >> 1;         // 0..127
    const int lc4  = (t & 1) * 4;    // 0 or 4

    float acc[8][8];
    #pragma unroll
    for (int i = 0; i < 8; i++)
        #pragma unroll
        for (int j = 0; j < 8; j++) acc[i][j] = 0.f;

    for (int k0 = 0; k0 < EMB; k0 += 8) {
        float4 av  = *(const float4*)(x + (size_t)(bm0 + lrow) * EMB + k0 + lc4);
        float4 bv4 = *(const float4*)(W + (size_t)(bn0 + lrow) * EMB + k0 + lc4);
        As[lc4+0][lrow] = av.x;  As[lc4+1][lrow] = av.y;
        As[lc4+2][lrow] = av.z;  As[lc4+3][lrow] = av.w;
        Bs[lc4+0][lrow] = bv4.x; Bs[lc4+1][lrow] = bv4.y;
        Bs[lc4+2][lrow] = bv4.z; Bs[lc4+3][lrow] = bv4.w;
        __syncthreads();

        #pragma unroll
        for (int kk = 0; kk < 8; kk++) {
            float4 a0 = *(const float4*)&As[kk][tr*8];
            float4 a1 = *(const float4*)&As[kk][tr*8 + 4];
            float4 b0 = *(const float4*)&Bs[kk][tc*8];
            float4 b1 = *(const float4*)&Bs[kk][tc*8 + 4];
            float ar[8] = {a0.x,a0.y,a0.z,a0.w,a1.x,a1.y,a1.z,a1.w};
            float br[8] = {b0.x,b0.y,b0.z,b0.w,b1.x,b1.y,b1.z,b1.w};
            #pragma unroll
            for (int m = 0; m < 8; m++)
                #pragma unroll
                for (int n = 0; n < 8; n++)
                    acc[m][n] = fmaf(ar[m], br[n], acc[m][n]);
        }
        __syncthreads();
    }

    // epilogue: + bias, scatter to [B,H,S,D]
    #pragma unroll
    for (int m = 0; m < 8; m++) {
        const int nrow = bm0 + tr*8 + m;
        const int b = nrow >> 12;           // /4096
        const int s = nrow & (SEQ - 1);
        #pragma unroll
        for (int n4 = 0; n4 < 8; n4 += 4) {
            const int j = bn0 + tc*8 + n4;
            const int h = j >> 6, d = j & 63;
            float4 v;
            v.x = acc[m][n4+0] + bias[j+0];
            v.y = acc[m][n4+1] + bias[j+1];
            v.z = acc[m][n4+2] + bias[j+2];
            v.w = acc[m][n4+3] + bias[j+3];
            *(float4*)(outp + ((size_t)(b*NH + h)*SEQ + s)*HD + d) = v;
        }
    }
}

// ---------------------------------------------------------------------------
// Kernel 2: flash attention (fp32, online softmax).
// grid = (SEQ/64, NB*NH), 256 threads. Each block: 64 Q rows x full KV sweep.
// Q,K stored d-major transposed in smem for conflict-free float4 LDS.
// ---------------------------------------------------------------------------
__global__ __launch_bounds__(256) void flash_kernel()
{
    extern __shared__ float sm[];
    float* Qt = sm;              // [64][64]  Qt[d*64 + row] (pre-scaled)
    float* Kt = sm + 4096;       // [64][64]  Kt[d*64 + kv]
    float* Vs = sm + 8192;       // [64][64]  Vs[kv*64 + d]
    float* Pt = sm + 12288;      // [64][65]  Pt[kv*65 + row]

    const int t  = threadIdx.x;
    const int tr = t >> 4;       // 0..15 -> score rows tr*4..+3
    const int tc = t & 15;       // 0..15 -> score cols / d cols tc*4..+3
    const int bh = blockIdx.y;
    const int q0 = blockIdx.x * 64;

    const float* Qp = g_Q + (size_t)bh * SEQ * HD;
    const float* Kp = g_K + (size_t)bh * SEQ * HD;
    const float* Vp = g_V + (size_t)bh * SEQ * HD;
    float*       Op = g_O + (size_t)bh * SEQ * HD;

    // load Q tile transposed, pre-scaled by 1/sqrt(64)
    {
        const int r  = t >> 2;
        const int d0 = (t & 3) * 16;
        const float* src = Qp + (size_t)(q0 + r) * HD + d0;
        #pragma unroll
        for (int i = 0; i < 4; i++) {
            float4 v = *(const float4*)(src + i*4);
            const int d = d0 + i*4;
            Qt[(d+0)*64 + r] = v.x * 0.125f;
            Qt[(d+1)*64 + r] = v.y * 0.125f;
            Qt[(d+2)*64 + r] = v.z * 0.125f;
            Qt[(d+3)*64 + r] = v.w * 0.125f;
        }
    }

    float o[4][4];
    float m_i[4], l_i[4];
    #pragma unroll
    for (int i = 0; i < 4; i++) {
        m_i[i] = -INFINITY; l_i[i] = 0.f;
        #pragma unroll
        for (int j = 0; j < 4; j++) o[i][j] = 0.f;
    }

    for (int kv0 = 0; kv0 < SEQ; kv0 += 64) {
        // load K tile transposed
        {
            const int r  = t >> 2;
            const int d0 = (t & 3) * 16;
            const float* src = Kp + (size_t)(kv0 + r) * HD + d0;
            #pragma unroll
            for (int i = 0; i < 4; i++) {
                float4 v = *(const float4*)(src + i*4);
                const int d = d0 + i*4;
                Kt[(d+0)*64 + r] = v.x;
                Kt[(d+1)*64 + r] = v.y;
                Kt[(d+2)*64 + r] = v.z;
                Kt[(d+3)*64 + r] = v.w;
            }
        }
        // load V tile (natural layout)
        {
            const float4* src = (const float4*)(Vp + (size_t)kv0 * HD);
            float4* dst = (float4*)Vs;
            #pragma unroll
            for (int i = 0; i < 4; i++) dst[t + 256*i] = src[t + 256*i];
        }
        __syncthreads();

        // S = Q K^T   (scores in registers, 4x4 per thread)
        float sc[4][4];
        #pragma unroll
        for (int i = 0; i < 4; i++)
            #pragma unroll
            for (int j = 0; j < 4; j++) sc[i][j] = 0.f;

        #pragma unroll 8
        for (int d = 0; d < 64; d++) {
            float4 qv = *(const float4*)&Qt[d*64 + tr*4];
            float4 kv = *(const float4*)&Kt[d*64 + tc*4];
            sc[0][0] = fmaf(qv.x, kv.x, sc[0][0]);
            sc[0][1] = fmaf(qv.x, kv.y, sc[0][1]);
            sc[0][2] = fmaf(qv.x, kv.z, sc[0][2]);
            sc[0][3] = fmaf(qv.x, kv.w, sc[0][3]);
            sc[1][0] = fmaf(qv.y, kv.x, sc[1][0]);
            sc[1][1] = fmaf(qv.y, kv.y, sc[1][1]);
            sc[1][2] = fmaf(qv.y, kv.z, sc[1][2]);
            sc[1][3] = fmaf(qv.y, kv.w, sc[1][3]);
            sc[2][0] = fmaf(qv.z, kv.x, sc[2][0]);
            sc[2][1] = fmaf(qv.z, kv.y, sc[2][1]);
            sc[2][2] = fmaf(qv.z, kv.z, sc[2][2]);
            sc[2][3] = fmaf(qv.z, kv.w, sc[2][3]);
            sc[3][0] = fmaf(qv.w, kv.x, sc[3][0]);
            sc[3][1] = fmaf(qv.w, kv.y, sc[3][1]);
            sc[3][2] = fmaf(qv.w, kv.z, sc[3][2]);
            sc[3][3] = fmaf(qv.w, kv.w, sc[3][3]);
        }

        // online softmax (16-lane groups share a row set; shuffles stay in-group)
        #pragma unroll
        for (int i = 0; i < 4; i++) {
            float mx = fmaxf(fmaxf(sc[i][0], sc[i][1]), fmaxf(sc[i][2], sc[i][3]));
            mx = fmaxf(mx, __shfl_xor_sync(0xffffffffu, mx, 1));
            mx = fmaxf(mx, __shfl_xor_sync(0xffffffffu, mx, 2));
            mx = fmaxf(mx, __shfl_xor_sync(0xffffffffu, mx, 4));
            mx = fmaxf(mx, __shfl_xor_sync(0xffffffffu, mx, 8));
            const float mnew  = fmaxf(m_i[i], mx);
            const float alpha = __expf(m_i[i] - mnew);
            float rs = 0.f;
            #pragma unroll
            for (int j = 0; j < 4; j++) {
                const float p = __expf(sc[i][j] - mnew);
                sc[i][j] = p;
                rs += p;
            }
            rs += __shfl_xor_sync(0xffffffffu, rs, 1);
            rs += __shfl_xor_sync(0xffffffffu, rs, 2);
            rs += __shfl_xor_sync(0xffffffffu, rs, 4);
            rs += __shfl_xor_sync(0xffffffffu, rs, 8);
            l_i[i] = l_i[i] * alpha + rs;
            m_i[i] = mnew;
            o[i][0] *= alpha; o[i][1] *= alpha; o[i][2] *= alpha; o[i][3] *= alpha;
        }

        // stage P transposed: Pt[kv][row]
        #pragma unroll
        for (int j = 0; j < 4; j++)
            #pragma unroll
            for (int i = 0; i < 4; i++)
                Pt[(tc*4 + j)*65 + tr*4 + i] = sc[i][j];
        __syncthreads();

        // O += P V
        #pragma unroll 8
        for (int kv = 0; kv < 64; kv++) {
            float4 vv = *(const float4*)&Vs[kv*64 + tc*4];
            const float p0 = Pt[kv*65 + tr*4 + 0];
            const float p1 = Pt[kv*65 + tr*4 + 1];
            const float p2 = Pt[kv*65 + tr*4 + 2];
            const float p3 = Pt[kv*65 + tr*4 + 3];
            o[0][0] = fmaf(p0, vv.x, o[0][0]);
            o[0][1] = fmaf(p0, vv.y, o[0][1]);
            o[0][2] = fmaf(p0, vv.z, o[0][2]);
            o[0][3] = fmaf(p0, vv.w, o[0][3]);
            o[1][0] = fmaf(p1, vv.x, o[1][0]);
            o[1][1] = fmaf(p1, vv.y, o[1][1]);
            o[1][2] = fmaf(p1, vv.z, o[1][2]);
            o[1][3] = fmaf(p1, vv.w, o[1][3]);
            o[2][0] = fmaf(p2, vv.x, o[2][0]);
            o[2][1] = fmaf(p2, vv.y, o[2][1]);
            o[2][2] = fmaf(p2, vv.z, o[2][2]);
            o[2][3] = fmaf(p2, vv.w, o[2][3]);
            o[3][0] = fmaf(p3, vv.x, o[3][0]);
            o[3][1] = fmaf(p3, vv.y, o[3][1]);
            o[3][2] = fmaf(p3, vv.z, o[3][2]);
            o[3][3] = fmaf(p3, vv.w, o[3][3]);
        }
        __syncthreads();
    }

    // finalize + store O
    #pragma unroll
    for (int i = 0; i < 4; i++) {
        const float inv = 1.f / l_i[i];
        float4 v = make_float4(o[i][0]*inv, o[i][1]*inv, o[i][2]*inv, o[i][3]*inv);
        *(float4*)(Op + (size_t)(q0 + tr*4 + i)*HD + tc*4) = v;
    }
}

// ---------------------------------------------------------------------------
// Kernel 3: out = O @ Wo^T + bo + x   (A gathered from [B,H,S,D])
// grid = (NROWS/128, EMB/128), 256 threads.
// ---------------------------------------------------------------------------
__global__ __launch_bounds__(256) void out_proj_kernel(
    const float* __restrict__ x,
    const float* __restrict__ Wo, const float* __restrict__ bo,
    float* __restrict__ out)
{
    __shared__ float As[8][128];
    __shared__ float Bs[8][128];

    const int t   = threadIdx.x;
    const int tr  = t >> 4;
    const int tc  = t & 15;
    const int bm0 = blockIdx.x * 128;
    const int bn0 = blockIdx.y * 128;
    const int lrow = t >> 1;
    const int lc4  = (t & 1) * 4;

    const int nrowA = bm0 + lrow;
    const int bA = nrowA >> 12;
    const int sA = nrowA & (SEQ - 1);

    float acc[8][8];
    #pragma unroll
    for (int i = 0; i < 8; i++)
        #pragma unroll
        for (int j = 0; j < 8; j++) acc[i][j] = 0.f;

    for (int k0 = 0; k0 < EMB; k0 += 8) {
        const int e = k0 + lc4;
        const int h = e >> 6, d = e & 63;    // 4 consecutive d stay in one head
        float4 av  = *(const float4*)(g_O + ((size_t)(bA*NH + h)*SEQ + sA)*HD + d);
        float4 bv4 = *(const float4*)(Wo + (size_t)(bn0 + lrow) * EMB + k0 + lc4);
        As[lc4+0][lrow] = av.x;  As[lc4+1][lrow] = av.y;
        As[lc4+2][lrow] = av.z;  As[lc4+3][lrow] = av.w;
        Bs[lc4+0][lrow] = bv4.x; Bs[lc4+1][lrow] = bv4.y;
        Bs[lc4+2][lrow] = bv4.z; Bs[lc4+3][lrow] = bv4.w;
        __syncthreads();

        #pragma unroll
        for (int kk = 0; kk < 8; kk++) {
            float4 a0 = *(const float4*)&As[kk][tr*8];
            float4 a1 = *(const float4*)&As[kk][tr*8 + 4];
            float4 b0 = *(const float4*)&Bs[kk][tc*8];
            float4 b1 = *(const float4*)&Bs[kk][tc*8 + 4];
            float ar[8] = {a0.x,a0.y,a0.z,a0.w,a1.x,a1.y,a1.z,a1.w};
            float br[8] = {b0.x,b0.y,b0.z,b0.w,b1.x,b1.y,b1.z,b1.w};
            #pragma unroll
            for (int m = 0; m < 8; m++)
                #pragma unroll
                for (int n = 0; n < 8; n++)
                    acc[m][n] = fmaf(ar[m], br[n], acc[m][n]);
        }
        __syncthreads();
    }

    // epilogue: + bo + residual x
    #pragma unroll
    for (int m = 0; m < 8; m++) {
        const int nrow = bm0 + tr*8 + m;
        #pragma unroll
        for (int n4 = 0; n4 < 8; n4 += 4) {
            const int j = bn0 + tc*8 + n4;
            float4 xr = *(const float4*)(x + (size_t)nrow*EMB + j);
            float4 v;
            v.x = acc[m][n4+0] + bo[j+0] + xr.x;
            v.y = acc[m][n4+1] + bo[j+1] + xr.y;
            v.z = acc[m][n4+2] + bo[j+2] + xr.z;
            v.w = acc[m][n4+3] + bo[j+3] + xr.w;
            *(float4*)(out + (size_t)nrow*EMB + j) = v;
        }
    }
}

// ---------------------------------------------------------------------------
extern "C" void kernel_launch(void* const* d_in, const int* in_sizes, int n_in,
                              void* d_out, int out_size)
{
    const float* x  = (const float*)d_in[0];
    const float* Wq = (const float*)d_in[1];
    const float* bq = (const float*)d_in[2];
    const float* Wk = (const float*)d_in[3];
    const float* bk = (const float*)d_in[4];
    const float* Wv = (const float*)d_in[5];
    const float* bv = (const float*)d_in[6];
    const float* Wo = (const float*)d_in[7];
    const float* bo = (const float*)d_in[8];
    float* out = (float*)d_out;

    const int flash_smem = 16448 * 4;   // Qt+Kt+Vs (3*16KB) + Pt (64*65*4)
    cudaFuncSetAttribute(flash_kernel,
                         cudaFuncAttributeMaxDynamicSharedMemorySize, flash_smem);

    proj_qkv_kernel<<<dim3(NROWS/128, EMB/128, 3), 256>>>(x, Wq, bq, Wk, bk, Wv, bv);
    flash_kernel<<<dim3(SEQ/64, NB*NH), 256, flash_smem>>>();
    out_proj_kernel<<<dim3(NROWS/128, EMB/128), 256>>>(x, Wo, bo, out);
}

// round 3
// speedup vs baseline: 1.1051x; 1.1051x over previous
#include <cuda_runtime.h>
#include <cuda_bf16.h>
#include <math.h>
#include <stdint.h>

#define NB   2
#define SEQ  4096
#define EMB  512
#define NH   8
#define HD   64
#define NROWS (NB*SEQ)   // 8192

// Scratch (allocation-free): [B,H,S,D] layouts, 16 MB each.
__device__ float g_Q[NB*NH*SEQ*HD];
__device__ float g_K[NB*NH*SEQ*HD];
__device__ float g_V[NB*NH*SEQ*HD];
__device__ float g_O[NB*NH*SEQ*HD];

// ============================ helpers ============================
static __device__ __forceinline__ uint32_t smem_u32(const void* p) {
    uint32_t a;
    asm("{ .reg .u64 t; cvta.to.shared.u64 t, %1; cvt.u32.u64 %0, t; }"
        : "=r"(a) : "l"(p));
    return a;
}
static __device__ __forceinline__ float ex2f(float x) {
    float r;
    asm("ex2.approx.f32 %0, %1;" : "=f"(r) : "f"(x));
    return r;
}
static __device__ __forceinline__ uint32_t bf2(float a, float b) {
    __nv_bfloat162 h = __floats2bfloat162_rn(a, b);   // .x=a (low), .y=b (high)
    return *reinterpret_cast<uint32_t*>(&h);
}
// residual pair vs packed-hi (low half holds 'a')
static __device__ __forceinline__ uint32_t lo_res(uint32_t h, float a, float b) {
    float ra = a - __uint_as_float(h << 16);
    float rb = b - __uint_as_float(h & 0xffff0000u);
    return bf2(ra, rb);
}
static __device__ __forceinline__ void ldsm4(uint32_t r[4], uint32_t addr) {
    asm volatile("ldmatrix.sync.aligned.m8n8.x4.shared.b16 {%0,%1,%2,%3}, [%4];"
                 : "=r"(r[0]), "=r"(r[1]), "=r"(r[2]), "=r"(r[3]) : "r"(addr));
}
static __device__ __forceinline__ void mma16816(float c[4], const uint32_t a[4],
                                                uint32_t b0, uint32_t b1) {
    asm volatile(
        "mma.sync.aligned.m16n8k16.row.col.f32.bf16.bf16.f32 "
        "{%0,%1,%2,%3}, {%4,%5,%6,%7}, {%8,%9}, {%0,%1,%2,%3};"
        : "+f"(c[0]), "+f"(c[1]), "+f"(c[2]), "+f"(c[3])
        : "r"(a[0]), "r"(a[1]), "r"(a[2]), "r"(a[3]), "r"(b0), "r"(b1));
}

// ============================ flash smem layout ============================
#define BQ   128
#define BKV  64
#define LDE  72            // bf16 elems per row (64 + 8 pad)
#define LDB  (LDE*2)       // 144 bytes
#define OQ_H 0
#define OQ_L (OQ_H + BQ*LDB)     // 18432
#define OK_H (OQ_L + BQ*LDB)     // 36864
#define OK_L (OK_H + BKV*LDB)    // 46080
#define OV_H (OK_L + BKV*LDB)    // 55296  (Vt: [d][kv])
#define OV_L (OV_H + HD*LDB)     // 64512
#define SMEM_FLASH (OV_L + HD*LDB)  // 73728

// ---------------------------------------------------------------------------
// Kernel 1: QKV projection (SIMT fp32 GEMM, unchanged).
// ---------------------------------------------------------------------------
__global__ __launch_bounds__(256) void proj_qkv_kernel(
    const float* __restrict__ x,
    const float* __restrict__ Wq, const float* __restrict__ bq,
    const float* __restrict__ Wk, const float* __restrict__ bk,
    const float* __restrict__ Wv, const float* __restrict__ bv)
{
    __shared__ float As[8][128];
    __shared__ float Bs[8][128];

    const float* W; const float* bias; float* outp;
    if (blockIdx.z == 0)      { W = Wq; bias = bq; outp = g_Q; }
    else if (blockIdx.z == 1) { W = Wk; bias = bk; outp = g_K; }
    else                      { W = Wv; bias = bv; outp = g_V; }

    const int t   = threadIdx.x;
    const int tr  = t >> 4;
    const int tc  = t & 15;
    const int bm0 = blockIdx.x * 128;
    const int bn0 = blockIdx.y * 128;
    const int lrow = t >> 1;
    const int lc4  = (t & 1) * 4;

    float acc[8][8];
    #pragma unroll
    for (int i = 0; i < 8; i++)
        #pragma unroll
        for (int j = 0; j < 8; j++) acc[i][j] = 0.f;

    for (int k0 = 0; k0 < EMB; k0 += 8) {
        float4 av  = *(const float4*)(x + (size_t)(bm0 + lrow) * EMB + k0 + lc4);
        float4 bv4 = *(const float4*)(W + (size_t)(bn0 + lrow) * EMB + k0 + lc4);
        As[lc4+0][lrow] = av.x;  As[lc4+1][lrow] = av.y;
        As[lc4+2][lrow] = av.z;  As[lc4+3][lrow] = av.w;
        Bs[lc4+0][lrow] = bv4.x; Bs[lc4+1][lrow] = bv4.y;
        Bs[lc4+2][lrow] = bv4.z; Bs[lc4+3][lrow] = bv4.w;
        __syncthreads();

        #pragma unroll
        for (int kk = 0; kk < 8; kk++) {
            float4 a0 = *(const float4*)&As[kk][tr*8];
            float4 a1 = *(const float4*)&As[kk][tr*8 + 4];
            float4 b0 = *(const float4*)&Bs[kk][tc*8];
            float4 b1 = *(const float4*)&Bs[kk][tc*8 + 4];
            float ar[8] = {a0.x,a0.y,a0.z,a0.w,a1.x,a1.y,a1.z,a1.w};
            float br[8] = {b0.x,b0.y,b0.z,b0.w,b1.x,b1.y,b1.z,b1.w};
            #pragma unroll
            for (int m = 0; m < 8; m++)
                #pragma unroll
                for (int n = 0; n < 8; n++)
                    acc[m][n] = fmaf(ar[m], br[n], acc[m][n]);
        }
        __syncthreads();
    }

    #pragma unroll
    for (int m = 0; m < 8; m++) {
        const int nrow = bm0 + tr*8 + m;
        const int b = nrow >> 12;
        const int s = nrow & (SEQ - 1);
        #pragma unroll
        for (int n4 = 0; n4 < 8; n4 += 4) {
            const int j = bn0 + tc*8 + n4;
            const int h = j >> 6, d = j & 63;
            float4 v;
            v.x = acc[m][n4+0] + bias[j+0];
            v.y = acc[m][n4+1] + bias[j+1];
            v.z = acc[m][n4+2] + bias[j+2];
            v.w = acc[m][n4+3] + bias[j+3];
            *(float4*)(outp + ((size_t)(b*NH + h)*SEQ + s)*HD + d) = v;
        }
    }
}

// ---------------------------------------------------------------------------
// Kernel 2: flash attention on mma.sync bf16 (hi/lo split, 3-term).
// 8 warps, 128 Q rows per CTA, KV tiles of 64. grid = (SEQ/128, NB*NH).
// ---------------------------------------------------------------------------
__global__ void __launch_bounds__(256, 1) flash_mma()
{
    extern __shared__ char smem[];
    const uint32_t sb = smem_u32(smem);

    const int t    = threadIdx.x;
    const int wid  = t >> 5;
    const int lane = t & 31;
    const int bh   = blockIdx.y;
    const int q0   = blockIdx.x * BQ;

    const float* Qp = g_Q + (size_t)bh * SEQ * HD;
    const float* Kp = g_K + (size_t)bh * SEQ * HD;
    const float* Vp = g_V + (size_t)bh * SEQ * HD;
    float*       Op = g_O + (size_t)bh * SEQ * HD;

    // ---- stage Q (scaled by (1/sqrt(64))*log2(e)), hi/lo split ----
    const float qscale = 0.125f * 1.4426950408889634f;
    #pragma unroll
    for (int i = 0; i < 8; i++) {
        int j = t + 256 * i;               // 0..2047 : 128 rows x 16 col-groups
        int r = j >> 4, c4 = (j & 15) * 4;
        float4 v = *(const float4*)(Qp + (size_t)(q0 + r) * HD + c4);
        v.x *= qscale; v.y *= qscale; v.z *= qscale; v.w *= qscale;
        uint32_t h0 = bf2(v.x, v.y), h1 = bf2(v.z, v.w);
        uint32_t l0 = lo_res(h0, v.x, v.y), l1 = lo_res(h1, v.z, v.w);
        uint32_t off = (uint32_t)r * LDB + (uint32_t)c4 * 2u;
        *(uint2*)(smem + OQ_H + off) = make_uint2(h0, h1);
        *(uint2*)(smem + OQ_L + off) = make_uint2(l0, l1);
    }

    // per-warp fragment address bases
    const int m0 = wid * 16;
    const uint32_t a_off = (uint32_t)(m0 + (lane & 15)) * LDB + ((uint32_t)(lane >> 4) << 4);
    const uint32_t b_off = (uint32_t)((lane & 7) + ((lane >> 4) << 3)) * LDB
                         + ((uint32_t)((lane >> 3) & 1) << 4);
    const uint32_t aQH = sb + OQ_H + a_off;
    const uint32_t aQL = sb + OQ_L + a_off;
    const uint32_t bKH = sb + OK_H + b_off;
    const uint32_t bKL = sb + OK_L + b_off;
    const uint32_t bVH = sb + OV_H + b_off;
    const uint32_t bVL = sb + OV_L + b_off;

    float m0r = -INFINITY, m1r = -INFINITY, l0r = 0.f, l1r = 0.f;
    float oc[8][4];
    #pragma unroll
    for (int j = 0; j < 8; j++)
        #pragma unroll
        for (int k = 0; k < 4; k++) oc[j][k] = 0.f;

    for (int kv0 = 0; kv0 < SEQ; kv0 += BKV) {
        // ---- stage K [kv][d] hi/lo and V transposed [d][kv] hi/lo ----
        #pragma unroll
        for (int i = 0; i < 4; i++) {
            int j = t + 256 * i;           // 0..1023 : 64 rows x 16 col-groups
            int r = j >> 4, c4 = (j & 15) * 4;
            float4 v = *(const float4*)(Kp + (size_t)(kv0 + r) * HD + c4);
            uint32_t h0 = bf2(v.x, v.y), h1 = bf2(v.z, v.w);
            uint32_t l0 = lo_res(h0, v.x, v.y), l1 = lo_res(h1, v.z, v.w);
            uint32_t off = (uint32_t)r * LDB + (uint32_t)c4 * 2u;
            *(uint2*)(smem + OK_H + off) = make_uint2(h0, h1);
            *(uint2*)(smem + OK_L + off) = make_uint2(l0, l1);
        }
        #pragma unroll
        for (int i = 0; i < 4; i++) {
            int j = t + 256 * i;
            int r = j >> 4, c4 = (j & 15) * 4;   // r = kv, c4 = d
            float4 v = *(const float4*)(Vp + (size_t)(kv0 + r) * HD + c4);
            float vv[4] = {v.x, v.y, v.z, v.w};
            #pragma unroll
            for (int k = 0; k < 4; k++) {
                __nv_bfloat16 hb = __float2bfloat16(vv[k]);
                __nv_bfloat16 lb = __float2bfloat16(vv[k] - __bfloat162float(hb));
                uint32_t off = (uint32_t)(c4 + k) * LDB + (uint32_t)r * 2u;
                *(__nv_bfloat16*)(smem + OV_H + off) = hb;
                *(__nv_bfloat16*)(smem + OV_L + off) = lb;
            }
        }
        __syncthreads();

        // ---- S = Q K^T (3-term split) ----
        float sc[8][4];
        #pragma unroll
        for (int j = 0; j < 8; j++)
            #pragma unroll
            for (int k = 0; k < 4; k++) sc[j][k] = 0.f;

        #pragma unroll
        for (int kk = 0; kk < 4; kk++) {
            uint32_t aH[4], aL[4];
            ldsm4(aH, aQH + kk * 32u);
            ldsm4(aL, aQL + kk * 32u);
            #pragma unroll
            for (int j = 0; j < 4; j++) {
                uint32_t bH[4], bL[4];
                ldsm4(bH, bKH + (uint32_t)j * 16u * LDB + kk * 32u);
                ldsm4(bL, bKL + (uint32_t)j * 16u * LDB + kk * 32u);
                mma16816(sc[2*j],   aH, bH[0], bH[1]);
                mma16816(sc[2*j+1], aH, bH[2], bH[3]);
                mma16816(sc[2*j],   aH, bL[0], bL[1]);
                mma16816(sc[2*j+1], aH, bL[2], bL[3]);
                mma16816(sc[2*j],   aL, bH[0], bH[1]);
                mma16816(sc[2*j+1], aL, bH[2], bH[3]);
            }
        }

        // ---- online softmax (base-2). rows: g=lane>>2 and g+8 ----
        float mx0 = -INFINITY, mx1 = -INFINITY;
        #pragma unroll
        for (int j = 0; j < 8; j++) {
            mx0 = fmaxf(mx0, fmaxf(sc[j][0], sc[j][1]));
            mx1 = fmaxf(mx1, fmaxf(sc[j][2], sc[j][3]));
        }
        mx0 = fmaxf(mx0, __shfl_xor_sync(0xffffffffu, mx0, 1));
        mx0 = fmaxf(mx0, __shfl_xor_sync(0xffffffffu, mx0, 2));
        mx1 = fmaxf(mx1, __shfl_xor_sync(0xffffffffu, mx1, 1));
        mx1 = fmaxf(mx1, __shfl_xor_sync(0xffffffffu, mx1, 2));
        const float mn0 = fmaxf(m0r, mx0);
        const float mn1 = fmaxf(m1r, mx1);
        const float al0 = ex2f(m0r - mn0);
        const float al1 = ex2f(m1r - mn1);
        m0r = mn0; m1r = mn1;

        float s0 = 0.f, s1 = 0.f;
        uint32_t pH[4][4], pL[4][4];
        #pragma unroll
        for (int kk = 0; kk < 4; kk++) {
            float p00 = ex2f(sc[2*kk][0]   - mn0), p01 = ex2f(sc[2*kk][1]   - mn0);
            float p10 = ex2f(sc[2*kk][2]   - mn1), p11 = ex2f(sc[2*kk][3]   - mn1);
            float q00 = ex2f(sc[2*kk+1][0] - mn0), q01 = ex2f(sc[2*kk+1][1] - mn0);
            float q10 = ex2f(sc[2*kk+1][2] - mn1), q11 = ex2f(sc[2*kk+1][3] - mn1);
            s0 += p00 + p01 + q00 + q01;
            s1 += p10 + p11 + q10 + q11;
            pH[kk][0] = bf2(p00, p01);  pL[kk][0] = lo_res(pH[kk][0], p00, p01);
            pH[kk][1] = bf2(p10, p11);  pL[kk][1] = lo_res(pH[kk][1], p10, p11);
            pH[kk][2] = bf2(q00, q01);  pL[kk][2] = lo_res(pH[kk][2], q00, q01);
            pH[kk][3] = bf2(q10, q11);  pL[kk][3] = lo_res(pH[kk][3], q10, q11);
        }
        s0 += __shfl_xor_sync(0xffffffffu, s0, 1);
        s0 += __shfl_xor_sync(0xffffffffu, s0, 2);
        s1 += __shfl_xor_sync(0xffffffffu, s1, 1);
        s1 += __shfl_xor_sync(0xffffffffu, s1, 2);
        l0r = l0r * al0 + s0;
        l1r = l1r * al1 + s1;

        #pragma unroll
        for (int j = 0; j < 8; j++) {
            oc[j][0] *= al0; oc[j][1] *= al0;
            oc[j][2] *= al1; oc[j][3] *= al1;
        }

        // ---- O += P V (3-term split) ----
        #pragma unroll
        for (int kk = 0; kk < 4; kk++) {
            #pragma unroll
            for (int j = 0; j < 4; j++) {
                uint32_t vH[4], vL[4];
                ldsm4(vH, bVH + (uint32_t)j * 16u * LDB + kk * 32u);
                ldsm4(vL, bVL + (uint32_t)j * 16u * LDB + kk * 32u);
                mma16816(oc[2*j],   pH[kk], vH[0], vH[1]);
                mma16816(oc[2*j+1], pH[kk], vH[2], vH[3]);
                mma16816(oc[2*j],   pH[kk], vL[0], vL[1]);
                mma16816(oc[2*j+1], pH[kk], vL[2], vL[3]);
                mma16816(oc[2*j],   pL[kk], vH[0], vH[1]);
                mma16816(oc[2*j+1], pL[kk], vH[2], vH[3]);
            }
        }
        __syncthreads();
    }

    // ---- finalize ----
    const float inv0 = 1.f / l0r;
    const float inv1 = 1.f / l1r;
    const int g  = lane >> 2;
    const int tg = lane & 3;
    float* r0p = Op + (size_t)(q0 + m0 + g)     * HD;
    float* r1p = Op + (size_t)(q0 + m0 + g + 8) * HD;
    #pragma unroll
    for (int j = 0; j < 8; j++) {
        float2 v0 = make_float2(oc[j][0] * inv0, oc[j][1] * inv0);
        float2 v1 = make_float2(oc[j][2] * inv1, oc[j][3] * inv1);
        *(float2*)(r0p + 8*j + 2*tg) = v0;
        *(float2*)(r1p + 8*j + 2*tg) = v1;
    }
}

// ---------------------------------------------------------------------------
// Kernel 3: out = O @ Wo^T + bo + x (SIMT fp32 GEMM, unchanged).
// ---------------------------------------------------------------------------
__global__ __launch_bounds__(256) void out_proj_kernel(
    const float* __restrict__ x,
    const float* __restrict__ Wo, const float* __restrict__ bo,
    float* __restrict__ out)
{
    __shared__ float As[8][128];
    __shared__ float Bs[8][128];

    const int t   = threadIdx.x;
    const int tr  = t >> 4;
    const int tc  = t & 15;
    const int bm0 = blockIdx.x * 128;
    const int bn0 = blockIdx.y * 128;
    const int lrow = t >> 1;
    const int lc4  = (t & 1) * 4;

    const int nrowA = bm0 + lrow;
    const int bA = nrowA >> 12;
    const int sA = nrowA & (SEQ - 1);

    float acc[8][8];
    #pragma unroll
    for (int i = 0; i < 8; i++)
        #pragma unroll
        for (int j = 0; j < 8; j++) acc[i][j] = 0.f;

    for (int k0 = 0; k0 < EMB; k0 += 8) {
        const int e = k0 + lc4;
        const int h = e >> 6, d = e & 63;
        float4 av  = *(const float4*)(g_O + ((size_t)(bA*NH + h)*SEQ + sA)*HD + d);
        float4 bv4 = *(const float4*)(Wo + (size_t)(bn0 + lrow) * EMB + k0 + lc4);
        As[lc4+0][lrow] = av.x;  As[lc4+1][lrow] = av.y;
        As[lc4+2][lrow] = av.z;  As[lc4+3][lrow] = av.w;
        Bs[lc4+0][lrow] = bv4.x; Bs[lc4+1][lrow] = bv4.y;
        Bs[lc4+2][lrow] = bv4.z; Bs[lc4+3][lrow] = bv4.w;
        __syncthreads();

        #pragma unroll
        for (int kk = 0; kk < 8; kk++) {
            float4 a0 = *(const float4*)&As[kk][tr*8];
            float4 a1 = *(const float4*)&As[kk][tr*8 + 4];
            float4 b0 = *(const float4*)&Bs[kk][tc*8];
            float4 b1 = *(const float4*)&Bs[kk][tc*8 + 4];
            float ar[8] = {a0.x,a0.y,a0.z,a0.w,a1.x,a1.y,a1.z,a1.w};
            float br[8] = {b0.x,b0.y,b0.z,b0.w,b1.x,b1.y,b1.z,b1.w};
            #pragma unroll
            for (int m = 0; m < 8; m++)
                #pragma unroll
                for (int n = 0; n < 8; n++)
                    acc[m][n] = fmaf(ar[m], br[n], acc[m][n]);
        }
        __syncthreads();
    }

    #pragma unroll
    for (int m = 0; m < 8; m++) {
        const int nrow = bm0 + tr*8 + m;
        #pragma unroll
        for (int n4 = 0; n4 < 8; n4 += 4) {
            const int j = bn0 + tc*8 + n4;
            float4 xr = *(const float4*)(x + (size_t)nrow*EMB + j);
            float4 v;
            v.x = acc[m][n4+0] + bo[j+0] + xr.x;
            v.y = acc[m][n4+1] + bo[j+1] + xr.y;
            v.z = acc[m][n4+2] + bo[j+2] + xr.z;
            v.w = acc[m][n4+3] + bo[j+3] + xr.w;
            *(float4*)(out + (size_t)nrow*EMB + j) = v;
        }
    }
}

// ---------------------------------------------------------------------------
extern "C" void kernel_launch(void* const* d_in, const int* in_sizes, int n_in,
                              void* d_out, int out_size)
{
    const float* x  = (const float*)d_in[0];
    const float* Wq = (const float*)d_in[1];
    const float* bq = (const float*)d_in[2];
    const float* Wk = (const float*)d_in[3];
    const float* bk = (const float*)d_in[4];
    const float* Wv = (const float*)d_in[5];
    const float* bv = (const float*)d_in[6];
    const float* Wo = (const float*)d_in[7];
    const float* bo = (const float*)d_in[8];
    float* out = (float*)d_out;

    cudaFuncSetAttribute(flash_mma,
                         cudaFuncAttributeMaxDynamicSharedMemorySize, SMEM_FLASH);

    proj_qkv_kernel<<<dim3(NROWS/128, EMB/128, 3), 256>>>(x, Wq, bq, Wk, bk, Wv, bv);
    flash_mma<<<dim3(SEQ/BQ, NB*NH), 256, SMEM_FLASH>>>();
    out_proj_kernel<<<dim3(NROWS/128, EMB/128), 256>>>(x, Wo, bo, out);
}

// round 4
// speedup vs baseline: 1.7250x; 1.5610x over previous
#include <cuda_runtime.h>
#include <cuda_bf16.h>
#include <math.h>
#include <stdint.h>

#define NB   2
#define SEQ  4096
#define EMB  512
#define NH   8
#define HD   64
#define NROWS (NB*SEQ)   // 8192

// Scratch (allocation-free): [B,H,S,D] layouts, 16 MB each.
__device__ float g_Q[NB*NH*SEQ*HD];
__device__ float g_K[NB*NH*SEQ*HD];
__device__ float g_V[NB*NH*SEQ*HD];
__device__ float g_O[NB*NH*SEQ*HD];

// ============================ helpers ============================
static __device__ __forceinline__ uint32_t smem_u32(const void* p) {
    uint32_t a;
    asm("{ .reg .u64 t; cvta.to.shared.u64 t, %1; cvt.u32.u64 %0, t; }"
        : "=r"(a) : "l"(p));
    return a;
}
static __device__ __forceinline__ float ex2f(float x) {
    float r;
    asm("ex2.approx.f32 %0, %1;" : "=f"(r) : "f"(x));
    return r;
}
static __device__ __forceinline__ uint32_t bf2(float a, float b) {
    __nv_bfloat162 h = __floats2bfloat162_rn(a, b);   // .x=a (low), .y=b (high)
    return *reinterpret_cast<uint32_t*>(&h);
}
// residual pair vs packed-hi (low half holds 'a')
static __device__ __forceinline__ uint32_t lo_res(uint32_t h, float a, float b) {
    float ra = a - __uint_as_float(h << 16);
    float rb = b - __uint_as_float(h & 0xffff0000u);
    return bf2(ra, rb);
}
static __device__ __forceinline__ void ldsm4(uint32_t r[4], uint32_t addr) {
    asm volatile("ldmatrix.sync.aligned.m8n8.x4.shared.b16 {%0,%1,%2,%3}, [%4];"
                 : "=r"(r[0]), "=r"(r[1]), "=r"(r[2]), "=r"(r[3]) : "r"(addr));
}
static __device__ __forceinline__ void mma16816(float c[4], const uint32_t a[4],
                                                uint32_t b0, uint32_t b1) {
    asm volatile(
        "mma.sync.aligned.m16n8k16.row.col.f32.bf16.bf16.f32 "
        "{%0,%1,%2,%3}, {%4,%5,%6,%7}, {%8,%9}, {%0,%1,%2,%3};"
        : "+f"(c[0]), "+f"(c[1]), "+f"(c[2]), "+f"(c[3])
        : "r"(a[0]), "r"(a[1]), "r"(a[2]), "r"(a[3]), "r"(b0), "r"(b1));
}

// ============================ flash smem layout ============================
#define BQ   128
#define BKV  64
#define LDE  72            // bf16 elems per row (64 + 8 pad)
#define LDB  (LDE*2)       // 144 bytes
#define OQ_H 0
#define OQ_L (OQ_H + BQ*LDB)     // 18432
#define OK_H (OQ_L + BQ*LDB)     // 36864
#define OK_L (OK_H + BKV*LDB)    // 46080
#define OV_H (OK_L + BKV*LDB)    // 55296  (Vt: [d][kv])
#define OV_L (OV_H + HD*LDB)     // 64512
#define SMEM_FLASH (OV_L + HD*LDB)  // 73728

// ---------------------------------------------------------------------------
// Kernel 1: QKV projection (SIMT fp32 GEMM, unchanged).
// ---------------------------------------------------------------------------
__global__ __launch_bounds__(256) void proj_qkv_kernel(
    const float* __restrict__ x,
    const float* __restrict__ Wq, const float* __restrict__ bq,
    const float* __restrict__ Wk, const float* __restrict__ bk,
    const float* __restrict__ Wv, const float* __restrict__ bv)
{
    __shared__ float As[8][128];
    __shared__ float Bs[8][128];

    const float* W; const float* bias; float* outp;
    if (blockIdx.z == 0)      { W = Wq; bias = bq; outp = g_Q; }
    else if (blockIdx.z == 1) { W = Wk; bias = bk; outp = g_K; }
    else                      { W = Wv; bias = bv; outp = g_V; }

    const int t   = threadIdx.x;
    const int tr  = t >> 4;
    const int tc  = t & 15;
    const int bm0 = blockIdx.x * 128;
    const int bn0 = blockIdx.y * 128;
    const int lrow = t >> 1;
    const int lc4  = (t & 1) * 4;

    float acc[8][8];
    #pragma unroll
    for (int i = 0; i < 8; i++)
        #pragma unroll
        for (int j = 0; j < 8; j++) acc[i][j] = 0.f;

    for (int k0 = 0; k0 < EMB; k0 += 8) {
        float4 av  = *(const float4*)(x + (size_t)(bm0 + lrow) * EMB + k0 + lc4);
        float4 bv4 = *(const float4*)(W + (size_t)(bn0 + lrow) * EMB + k0 + lc4);
        As[lc4+0][lrow] = av.x;  As[lc4+1][lrow] = av.y;
        As[lc4+2][lrow] = av.z;  As[lc4+3][lrow] = av.w;
        Bs[lc4+0][lrow] = bv4.x; Bs[lc4+1][lrow] = bv4.y;
        Bs[lc4+2][lrow] = bv4.z; Bs[lc4+3][lrow] = bv4.w;
        __syncthreads();

        #pragma unroll
        for (int kk = 0; kk < 8; kk++) {
            float4 a0 = *(const float4*)&As[kk][tr*8];
            float4 a1 = *(const float4*)&As[kk][tr*8 + 4];
            float4 b0 = *(const float4*)&Bs[kk][tc*8];
            float4 b1 = *(const float4*)&Bs[kk][tc*8 + 4];
            float ar[8] = {a0.x,a0.y,a0.z,a0.w,a1.x,a1.y,a1.z,a1.w};
            float br[8] = {b0.x,b0.y,b0.z,b0.w,b1.x,b1.y,b1.z,b1.w};
            #pragma unroll
            for (int m = 0; m < 8; m++)
                #pragma unroll
                for (int n = 0; n < 8; n++)
                    acc[m][n] = fmaf(ar[m], br[n], acc[m][n]);
        }
        __syncthreads();
    }

    #pragma unroll
    for (int m = 0; m < 8; m++) {
        const int nrow = bm0 + tr*8 + m;
        const int b = nrow >> 12;
        const int s = nrow & (SEQ - 1);
        #pragma unroll
        for (int n4 = 0; n4 < 8; n4 += 4) {
            const int j = bn0 + tc*8 + n4;
            const int h = j >> 6, d = j & 63;
            float4 v;
            v.x = acc[m][n4+0] + bias[j+0];
            v.y = acc[m][n4+1] + bias[j+1];
            v.z = acc[m][n4+2] + bias[j+2];
            v.w = acc[m][n4+3] + bias[j+3];
            *(float4*)(outp + ((size_t)(b*NH + h)*SEQ + s)*HD + d) = v;
        }
    }
}

// ---------------------------------------------------------------------------
// Kernel 2: flash attention on mma.sync bf16 (hi/lo split, 3-term).
// 8 warps, 128 Q rows per CTA, KV tiles of 64. grid = (SEQ/128, NB*NH).
// ---------------------------------------------------------------------------
__global__ void __launch_bounds__(256, 1) flash_mma()
{
    extern __shared__ char smem[];
    const uint32_t sb = smem_u32(smem);

    const int t    = threadIdx.x;
    const int wid  = t >> 5;
    const int lane = t & 31;
    const int bh   = blockIdx.y;
    const int q0   = blockIdx.x * BQ;

    const float* Qp = g_Q + (size_t)bh * SEQ * HD;
    const float* Kp = g_K + (size_t)bh * SEQ * HD;
    const float* Vp = g_V + (size_t)bh * SEQ * HD;
    float*       Op = g_O + (size_t)bh * SEQ * HD;

    // ---- stage Q (scaled by (1/sqrt(64))*log2(e)), hi/lo split ----
    const float qscale = 0.125f * 1.4426950408889634f;
    #pragma unroll
    for (int i = 0; i < 8; i++) {
        int j = t + 256 * i;               // 0..2047 : 128 rows x 16 col-groups
        int r = j >> 4, c4 = (j & 15) * 4;
        float4 v = *(const float4*)(Qp + (size_t)(q0 + r) * HD + c4);
        v.x *= qscale; v.y *= qscale; v.z *= qscale; v.w *= qscale;
        uint32_t h0 = bf2(v.x, v.y), h1 = bf2(v.z, v.w);
        uint32_t l0 = lo_res(h0, v.x, v.y), l1 = lo_res(h1, v.z, v.w);
        uint32_t off = (uint32_t)r * LDB + (uint32_t)c4 * 2u;
        *(uint2*)(smem + OQ_H + off) = make_uint2(h0, h1);
        *(uint2*)(smem + OQ_L + off) = make_uint2(l0, l1);
    }

    // per-warp fragment address bases
    const int m0 = wid * 16;
    const uint32_t a_off = (uint32_t)(m0 + (lane & 15)) * LDB + ((uint32_t)(lane >> 4) << 4);
    const uint32_t b_off = (uint32_t)((lane & 7) + ((lane >> 4) << 3)) * LDB
                         + ((uint32_t)((lane >> 3) & 1) << 4);
    const uint32_t aQH = sb + OQ_H + a_off;
    const uint32_t aQL = sb + OQ_L + a_off;
    const uint32_t bKH = sb + OK_H + b_off;
    const uint32_t bKL = sb + OK_L + b_off;
    const uint32_t bVH = sb + OV_H + b_off;
    const uint32_t bVL = sb + OV_L + b_off;

    float m0r = -INFINITY, m1r = -INFINITY, l0r = 0.f, l1r = 0.f;
    float oc[8][4];
    #pragma unroll
    for (int j = 0; j < 8; j++)
        #pragma unroll
        for (int k = 0; k < 4; k++) oc[j][k] = 0.f;

    for (int kv0 = 0; kv0 < SEQ; kv0 += BKV) {
        // ---- stage K [kv][d] hi/lo and V transposed [d][kv] hi/lo ----
        #pragma unroll
        for (int i = 0; i < 4; i++) {
            int j = t + 256 * i;           // 0..1023 : 64 rows x 16 col-groups
            int r = j >> 4, c4 = (j & 15) * 4;
            float4 v = *(const float4*)(Kp + (size_t)(kv0 + r) * HD + c4);
            uint32_t h0 = bf2(v.x, v.y), h1 = bf2(v.z, v.w);
            uint32_t l0 = lo_res(h0, v.x, v.y), l1 = lo_res(h1, v.z, v.w);
            uint32_t off = (uint32_t)r * LDB + (uint32_t)c4 * 2u;
            *(uint2*)(smem + OK_H + off) = make_uint2(h0, h1);
            *(uint2*)(smem + OK_L + off) = make_uint2(l0, l1);
        }
        #pragma unroll
        for (int i = 0; i < 4; i++) {
            int j = t + 256 * i;
            int r = j >> 4, c4 = (j & 15) * 4;   // r = kv, c4 = d
            float4 v = *(const float4*)(Vp + (size_t)(kv0 + r) * HD + c4);
            float vv[4] = {v.x, v.y, v.z, v.w};
            #pragma unroll
            for (int k = 0; k < 4; k++) {
                __nv_bfloat16 hb = __float2bfloat16(vv[k]);
                __nv_bfloat16 lb = __float2bfloat16(vv[k] - __bfloat162float(hb));
                uint32_t off = (uint32_t)(c4 + k) * LDB + (uint32_t)r * 2u;
                *(__nv_bfloat16*)(smem + OV_H + off) = hb;
                *(__nv_bfloat16*)(smem + OV_L + off) = lb;
            }
        }
        __syncthreads();

        // ---- S = Q K^T (3-term split) ----
        float sc[8][4];
        #pragma unroll
        for (int j = 0; j < 8; j++)
            #pragma unroll
            for (int k = 0; k < 4; k++) sc[j][k] = 0.f;

        #pragma unroll
        for (int kk = 0; kk < 4; kk++) {
            uint32_t aH[4], aL[4];
            ldsm4(aH, aQH + kk * 32u);
            ldsm4(aL, aQL + kk * 32u);
            #pragma unroll
            for (int j = 0; j < 4; j++) {
                uint32_t bH[4], bL[4];
                ldsm4(bH, bKH + (uint32_t)j * 16u * LDB + kk * 32u);
                ldsm4(bL, bKL + (uint32_t)j * 16u * LDB + kk * 32u);
                mma16816(sc[2*j],   aH, bH[0], bH[1]);
                mma16816(sc[2*j+1], aH, bH[2], bH[3]);
                mma16816(sc[2*j],   aH, bL[0], bL[1]);
                mma16816(sc[2*j+1], aH, bL[2], bL[3]);
                mma16816(sc[2*j],   aL, bH[0], bH[1]);
                mma16816(sc[2*j+1], aL, bH[2], bH[3]);
            }
        }

        // ---- online softmax (base-2). rows: g=lane>>2 and g+8 ----
        float mx0 = -INFINITY, mx1 = -INFINITY;
        #pragma unroll
        for (int j = 0; j < 8; j++) {
            mx0 = fmaxf(mx0, fmaxf(sc[j][0], sc[j][1]));
            mx1 = fmaxf(mx1, fmaxf(sc[j][2], sc[j][3]));
        }
        mx0 = fmaxf(mx0, __shfl_xor_sync(0xffffffffu, mx0, 1));
        mx0 = fmaxf(mx0, __shfl_xor_sync(0xffffffffu, mx0, 2));
        mx1 = fmaxf(mx1, __shfl_xor_sync(0xffffffffu, mx1, 1));
        mx1 = fmaxf(mx1, __shfl_xor_sync(0xffffffffu, mx1, 2));
        const float mn0 = fmaxf(m0r, mx0);
        const float mn1 = fmaxf(m1r, mx1);
        const float al0 = ex2f(m0r - mn0);
        const float al1 = ex2f(m1r - mn1);
        m0r = mn0; m1r = mn1;

        float s0 = 0.f, s1 = 0.f;
        uint32_t pH[4][4], pL[4][4];
        #pragma unroll
        for (int kk = 0; kk < 4; kk++) {
            float p00 = ex2f(sc[2*kk][0]   - mn0), p01 = ex2f(sc[2*kk][1]   - mn0);
            float p10 = ex2f(sc[2*kk][2]   - mn1), p11 = ex2f(sc[2*kk][3]   - mn1);
            float q00 = ex2f(sc[2*kk+1][0] - mn0), q01 = ex2f(sc[2*kk+1][1] - mn0);
            float q10 = ex2f(sc[2*kk+1][2] - mn1), q11 = ex2f(sc[2*kk+1][3] - mn1);
            s0 += p00 + p01 + q00 + q01;
            s1 += p10 + p11 + q10 + q11;
            pH[kk][0] = bf2(p00, p01);  pL[kk][0] = lo_res(pH[kk][0], p00, p01);
            pH[kk][1] = bf2(p10, p11);  pL[kk][1] = lo_res(pH[kk][1], p10, p11);
            pH[kk][2] = bf2(q00, q01);  pL[kk][2] = lo_res(pH[kk][2], q00, q01);
            pH[kk][3] = bf2(q10, q11);  pL[kk][3] = lo_res(pH[kk][3], q10, q11);
        }
        s0 += __shfl_xor_sync(0xffffffffu, s0, 1);
        s0 += __shfl_xor_sync(0xffffffffu, s0, 2);
        s1 += __shfl_xor_sync(0xffffffffu, s1, 1);
        s1 += __shfl_xor_sync(0xffffffffu, s1, 2);
        l0r = l0r * al0 + s0;
        l1r = l1r * al1 + s1;

        #pragma unroll
        for (int j = 0; j < 8; j++) {
            oc[j][0] *= al0; oc[j][1] *= al0;
            oc[j][2] *= al1; oc[j][3] *= al1;
        }

        // ---- O += P V (3-term split) ----
        #pragma unroll
        for (int kk = 0; kk < 4; kk++) {
            #pragma unroll
            for (int j = 0; j < 4; j++) {
                uint32_t vH[4], vL[4];
                ldsm4(vH, bVH + (uint32_t)j * 16u * LDB + kk * 32u);
                ldsm4(vL, bVL + (uint32_t)j * 16u * LDB + kk * 32u);
                mma16816(oc[2*j],   pH[kk], vH[0], vH[1]);
                mma16816(oc[2*j+1], pH[kk], vH[2], vH[3]);
                mma16816(oc[2*j],   pH[kk], vL[0], vL[1]);
                mma16816(oc[2*j+1], pH[kk], vL[2], vL[3]);
                mma16816(oc[2*j],   pL[kk], vH[0], vH[1]);
                mma16816(oc[2*j+1], pL[kk], vH[2], vH[3]);
            }
        }
        __syncthreads();
    }

    // ---- finalize ----
    const float inv0 = 1.f / l0r;
    const float inv1 = 1.f / l1r;
    const int g  = lane >> 2;
    const int tg = lane & 3;
    float* r0p = Op + (size_t)(q0 + m0 + g)     * HD;
    float* r1p = Op + (size_t)(q0 + m0 + g + 8) * HD;
    #pragma unroll
    for (int j = 0; j < 8; j++) {
        float2 v0 = make_float2(oc[j][0] * inv0, oc[j][1] * inv0);
        float2 v1 = make_float2(oc[j][2] * inv1, oc[j][3] * inv1);
        *(float2*)(r0p + 8*j + 2*tg) = v0;
        *(float2*)(r1p + 8*j + 2*tg) = v1;
    }
}

// ---------------------------------------------------------------------------
// Kernel 3: out = O @ Wo^T + bo + x (SIMT fp32 GEMM, unchanged).
// ---------------------------------------------------------------------------
__global__ __launch_bounds__(256) void out_proj_kernel(
    const float* __restrict__ x,
    const float* __restrict__ Wo, const float* __restrict__ bo,
    float* __restrict__ out)
{
    __shared__ float As[8][128];
    __shared__ float Bs[8][128];

    const int t   = threadIdx.x;
    const int tr  = t >> 4;
    const int tc  = t & 15;
    const int bm0 = blockIdx.x * 128;
    const int bn0 = blockIdx.y * 128;
    const int lrow = t >> 1;
    const int lc4  = (t & 1) * 4;

    const int nrowA = bm0 + lrow;
    const int bA = nrowA >> 12;
    const int sA = nrowA & (SEQ - 1);

    float acc[8][8];
    #pragma unroll
    for (int i = 0; i < 8; i++)
        #pragma unroll
        for (int j = 0; j < 8; j++) acc[i][j] = 0.f;

    for (int k0 = 0; k0 < EMB; k0 += 8) {
        const int e = k0 + lc4;
        const int h = e >> 6, d = e & 63;
        float4 av  = *(const float4*)(g_O + ((size_t)(bA*NH + h)*SEQ + sA)*HD + d);
        float4 bv4 = *(const float4*)(Wo + (size_t)(bn0 + lrow) * EMB + k0 + lc4);
        As[lc4+0][lrow] = av.x;  As[lc4+1][lrow] = av.y;
        As[lc4+2][lrow] = av.z;  As[lc4+3][lrow] = av.w;
        Bs[lc4+0][lrow] = bv4.x; Bs[lc4+1][lrow] = bv4.y;
        Bs[lc4+2][lrow] = bv4.z; Bs[lc4+3][lrow] = bv4.w;
        __syncthreads();

        #pragma unroll
        for (int kk = 0; kk < 8; kk++) {
            float4 a0 = *(const float4*)&As[kk][tr*8];
            float4 a1 = *(const float4*)&As[kk][tr*8 + 4];
            float4 b0 = *(const float4*)&Bs[kk][tc*8];
            float4 b1 = *(const float4*)&Bs[kk][tc*8 + 4];
            float ar[8] = {a0.x,a0.y,a0.z,a0.w,a1.x,a1.y,a1.z,a1.w};
            float br[8] = {b0.x,b0.y,b0.z,b0.w,b1.x,b1.y,b1.z,b1.w};
            #pragma unroll
            for (int m = 0; m < 8; m++)
                #pragma unroll
                for (int n = 0; n < 8; n++)
                    acc[m][n] = fmaf(ar[m], br[n], acc[m][n]);
        }
        __syncthreads();
    }

    #pragma unroll
    for (int m = 0; m < 8; m++) {
        const int nrow = bm0 + tr*8 + m;
        #pragma unroll
        for (int n4 = 0; n4 < 8; n4 += 4) {
            const int j = bn0 + tc*8 + n4;
            float4 xr = *(const float4*)(x + (size_t)nrow*EMB + j);
            float4 v;
            v.x = acc[m][n4+0] + bo[j+0] + xr.x;
            v.y = acc[m][n4+1] + bo[j+1] + xr.y;
            v.z = acc[m][n4+2] + bo[j+2] + xr.z;
            v.w = acc[m][n4+3] + bo[j+3] + xr.w;
            *(float4*)(out + (size_t)nrow*EMB + j) = v;
        }
    }
}

// ---------------------------------------------------------------------------
extern "C" void kernel_launch(void* const* d_in, const int* in_sizes, int n_in,
                              void* d_out, int out_size)
{
    const float* x  = (const float*)d_in[0];
    const float* Wq = (const float*)d_in[1];
    const float* bq = (const float*)d_in[2];
    const float* Wk = (const float*)d_in[3];
    const float* bk = (const float*)d_in[4];
    const float* Wv = (const float*)d_in[5];
    const float* bv = (const float*)d_in[6];
    const float* Wo = (const float*)d_in[7];
    const float* bo = (const float*)d_in[8];
    float* out = (float*)d_out;

    cudaFuncSetAttribute(flash_mma,
                         cudaFuncAttributeMaxDynamicSharedMemorySize, SMEM_FLASH);

    proj_qkv_kernel<<<dim3(NROWS/128, EMB/128, 3), 256>>>(x, Wq, bq, Wk, bk, Wv, bv);
    flash_mma<<<dim3(SEQ/BQ, NB*NH), 256, SMEM_FLASH>>>();
    out_proj_kernel<<<dim3(NROWS/128, EMB/128), 256>>>(x, Wo, bo, out);
}

// round 5
// speedup vs baseline: 1.7254x; 1.0002x over previous
#include <cuda_runtime.h>
#include <cuda_bf16.h>
#include <math.h>
#include <stdint.h>

#define NB   2
#define SEQ  4096
#define EMB  512
#define NH   8
#define HD   64
#define NROWS (NB*SEQ)   // 8192

// Scratch (allocation-free): [B,H,S,D] layouts, 16 MB each.
__device__ float g_Q[NB*NH*SEQ*HD];
__device__ float g_K[NB*NH*SEQ*HD];
__device__ float g_V[NB*NH*SEQ*HD];
__device__ float g_O[NB*NH*SEQ*HD];

// ============================ helpers ============================
static __device__ __forceinline__ uint32_t smem_u32(const void* p) {
    uint32_t a;
    asm("{ .reg .u64 t; cvta.to.shared.u64 t, %1; cvt.u32.u64 %0, t; }"
        : "=r"(a) : "l"(p));
    return a;
}
static __device__ __forceinline__ float ex2f(float x) {
    float r;
    asm("ex2.approx.f32 %0, %1;" : "=f"(r) : "f"(x));
    return r;
}
static __device__ __forceinline__ uint32_t bf2(float a, float b) {
    __nv_bfloat162 h = __floats2bfloat162_rn(a, b);   // .x=a (low), .y=b (high)
    return *reinterpret_cast<uint32_t*>(&h);
}
// residual pair vs packed-hi (low half holds 'a')
static __device__ __forceinline__ uint32_t lo_res(uint32_t h, float a, float b) {
    float ra = a - __uint_as_float(h << 16);
    float rb = b - __uint_as_float(h & 0xffff0000u);
    return bf2(ra, rb);
}
static __device__ __forceinline__ void ldsm4(uint32_t r[4], uint32_t addr) {
    asm volatile("ldmatrix.sync.aligned.m8n8.x4.shared.b16 {%0,%1,%2,%3}, [%4];"
                 : "=r"(r[0]), "=r"(r[1]), "=r"(r[2]), "=r"(r[3]) : "r"(addr));
}
static __device__ __forceinline__ void mma16816(float c[4], const uint32_t a[4],
                                                uint32_t b0, uint32_t b1) {
    asm volatile(
        "mma.sync.aligned.m16n8k16.row.col.f32.bf16.bf16.f32 "
        "{%0,%1,%2,%3}, {%4,%5,%6,%7}, {%8,%9}, {%0,%1,%2,%3};"
        : "+f"(c[0]), "+f"(c[1]), "+f"(c[2]), "+f"(c[3])
        : "r"(a[0]), "r"(a[1]), "r"(a[2]), "r"(a[3]), "r"(b0), "r"(b1));
}

// ============================ flash smem layout ============================
#define BQ   128
#define BKV  64
#define LDE  72            // bf16 elems per row (64 + 8 pad)
#define LDB  (LDE*2)       // 144 bytes
#define OQ_H 0
#define OQ_L (OQ_H + BQ*LDB)     // 18432
#define OK_H (OQ_L + BQ*LDB)     // 36864
#define OK_L (OK_H + BKV*LDB)    // 46080
#define OV_H (OK_L + BKV*LDB)    // 55296  (Vt: [d][kv])
#define OV_L (OV_H + HD*LDB)     // 64512
#define SMEM_FLASH (OV_L + HD*LDB)  // 73728

// ---------------------------------------------------------------------------
// Kernel 1: QKV projection (SIMT fp32 GEMM, unchanged).
// ---------------------------------------------------------------------------
__global__ __launch_bounds__(256) void proj_qkv_kernel(
    const float* __restrict__ x,
    const float* __restrict__ Wq, const float* __restrict__ bq,
    const float* __restrict__ Wk, const float* __restrict__ bk,
    const float* __restrict__ Wv, const float* __restrict__ bv)
{
    __shared__ float As[8][128];
    __shared__ float Bs[8][128];

    const float* W; const float* bias; float* outp;
    if (blockIdx.z == 0)      { W = Wq; bias = bq; outp = g_Q; }
    else if (blockIdx.z == 1) { W = Wk; bias = bk; outp = g_K; }
    else                      { W = Wv; bias = bv; outp = g_V; }

    const int t   = threadIdx.x;
    const int tr  = t >> 4;
    const int tc  = t & 15;
    const int bm0 = blockIdx.x * 128;
    const int bn0 = blockIdx.y * 128;
    const int lrow = t >> 1;
    const int lc4  = (t & 1) * 4;

    float acc[8][8];
    #pragma unroll
    for (int i = 0; i < 8; i++)
        #pragma unroll
        for (int j = 0; j < 8; j++) acc[i][j] = 0.f;

    for (int k0 = 0; k0 < EMB; k0 += 8) {
        float4 av  = *(const float4*)(x + (size_t)(bm0 + lrow) * EMB + k0 + lc4);
        float4 bv4 = *(const float4*)(W + (size_t)(bn0 + lrow) * EMB + k0 + lc4);
        As[lc4+0][lrow] = av.x;  As[lc4+1][lrow] = av.y;
        As[lc4+2][lrow] = av.z;  As[lc4+3][lrow] = av.w;
        Bs[lc4+0][lrow] = bv4.x; Bs[lc4+1][lrow] = bv4.y;
        Bs[lc4+2][lrow] = bv4.z; Bs[lc4+3][lrow] = bv4.w;
        __syncthreads();

        #pragma unroll
        for (int kk = 0; kk < 8; kk++) {
            float4 a0 = *(const float4*)&As[kk][tr*8];
            float4 a1 = *(const float4*)&As[kk][tr*8 + 4];
            float4 b0 = *(const float4*)&Bs[kk][tc*8];
            float4 b1 = *(const float4*)&Bs[kk][tc*8 + 4];
            float ar[8] = {a0.x,a0.y,a0.z,a0.w,a1.x,a1.y,a1.z,a1.w};
            float br[8] = {b0.x,b0.y,b0.z,b0.w,b1.x,b1.y,b1.z,b1.w};
            #pragma unroll
            for (int m = 0; m < 8; m++)
                #pragma unroll
                for (int n = 0; n < 8; n++)
                    acc[m][n] = fmaf(ar[m], br[n], acc[m][n]);
        }
        __syncthreads();
    }

    #pragma unroll
    for (int m = 0; m < 8; m++) {
        const int nrow = bm0 + tr*8 + m;
        const int b = nrow >> 12;
        const int s = nrow & (SEQ - 1);
        #pragma unroll
        for (int n4 = 0; n4 < 8; n4 += 4) {
            const int j = bn0 + tc*8 + n4;
            const int h = j >> 6, d = j & 63;
            float4 v;
            v.x = acc[m][n4+0] + bias[j+0];
            v.y = acc[m][n4+1] + bias[j+1];
            v.z = acc[m][n4+2] + bias[j+2];
            v.w = acc[m][n4+3] + bias[j+3];
            *(float4*)(outp + ((size_t)(b*NH + h)*SEQ + s)*HD + d) = v;
        }
    }
}

// ---------------------------------------------------------------------------
// Kernel 2: flash attention on mma.sync bf16 (hi/lo split, 3-term).
// 8 warps, 128 Q rows per CTA, KV tiles of 64. grid = (SEQ/128, NB*NH).
// ---------------------------------------------------------------------------
__global__ void __launch_bounds__(256, 1) flash_mma()
{
    extern __shared__ char smem[];
    const uint32_t sb = smem_u32(smem);

    const int t    = threadIdx.x;
    const int wid  = t >> 5;
    const int lane = t & 31;
    const int bh   = blockIdx.y;
    const int q0   = blockIdx.x * BQ;

    const float* Qp = g_Q + (size_t)bh * SEQ * HD;
    const float* Kp = g_K + (size_t)bh * SEQ * HD;
    const float* Vp = g_V + (size_t)bh * SEQ * HD;
    float*       Op = g_O + (size_t)bh * SEQ * HD;

    // ---- stage Q (scaled by (1/sqrt(64))*log2(e)), hi/lo split ----
    const float qscale = 0.125f * 1.4426950408889634f;
    #pragma unroll
    for (int i = 0; i < 8; i++) {
        int j = t + 256 * i;               // 0..2047 : 128 rows x 16 col-groups
        int r = j >> 4, c4 = (j & 15) * 4;
        float4 v = *(const float4*)(Qp + (size_t)(q0 + r) * HD + c4);
        v.x *= qscale; v.y *= qscale; v.z *= qscale; v.w *= qscale;
        uint32_t h0 = bf2(v.x, v.y), h1 = bf2(v.z, v.w);
        uint32_t l0 = lo_res(h0, v.x, v.y), l1 = lo_res(h1, v.z, v.w);
        uint32_t off = (uint32_t)r * LDB + (uint32_t)c4 * 2u;
        *(uint2*)(smem + OQ_H + off) = make_uint2(h0, h1);
        *(uint2*)(smem + OQ_L + off) = make_uint2(l0, l1);
    }

    // per-warp fragment address bases
    const int m0 = wid * 16;
    const uint32_t a_off = (uint32_t)(m0 + (lane & 15)) * LDB + ((uint32_t)(lane >> 4) << 4);
    const uint32_t b_off = (uint32_t)((lane & 7) + ((lane >> 4) << 3)) * LDB
                         + ((uint32_t)((lane >> 3) & 1) << 4);
    const uint32_t aQH = sb + OQ_H + a_off;
    const uint32_t aQL = sb + OQ_L + a_off;
    const uint32_t bKH = sb + OK_H + b_off;
    const uint32_t bKL = sb + OK_L + b_off;
    const uint32_t bVH = sb + OV_H + b_off;
    const uint32_t bVL = sb + OV_L + b_off;

    float m0r = -INFINITY, m1r = -INFINITY, l0r = 0.f, l1r = 0.f;
    float oc[8][4];
    #pragma unroll
    for (int j = 0; j < 8; j++)
        #pragma unroll
        for (int k = 0; k < 4; k++) oc[j][k] = 0.f;

    for (int kv0 = 0; kv0 < SEQ; kv0 += BKV) {
        // ---- stage K [kv][d] hi/lo and V transposed [d][kv] hi/lo ----
        #pragma unroll
        for (int i = 0; i < 4; i++) {
            int j = t + 256 * i;           // 0..1023 : 64 rows x 16 col-groups
            int r = j >> 4, c4 = (j & 15) * 4;
            float4 v = *(const float4*)(Kp + (size_t)(kv0 + r) * HD + c4);
            uint32_t h0 = bf2(v.x, v.y), h1 = bf2(v.z, v.w);
            uint32_t l0 = lo_res(h0, v.x, v.y), l1 = lo_res(h1, v.z, v.w);
            uint32_t off = (uint32_t)r * LDB + (uint32_t)c4 * 2u;
            *(uint2*)(smem + OK_H + off) = make_uint2(h0, h1);
            *(uint2*)(smem + OK_L + off) = make_uint2(l0, l1);
        }
        #pragma unroll
        for (int i = 0; i < 4; i++) {
            int j = t + 256 * i;
            int r = j >> 4, c4 = (j & 15) * 4;   // r = kv, c4 = d
            float4 v = *(const float4*)(Vp + (size_t)(kv0 + r) * HD + c4);
            float vv[4] = {v.x, v.y, v.z, v.w};
            #pragma unroll
            for (int k = 0; k < 4; k++) {
                __nv_bfloat16 hb = __float2bfloat16(vv[k]);
                __nv_bfloat16 lb = __float2bfloat16(vv[k] - __bfloat162float(hb));
                uint32_t off = (uint32_t)(c4 + k) * LDB + (uint32_t)r * 2u;
                *(__nv_bfloat16*)(smem + OV_H + off) = hb;
                *(__nv_bfloat16*)(smem + OV_L + off) = lb;
            }
        }
        __syncthreads();

        // ---- S = Q K^T (3-term split) ----
        float sc[8][4];
        #pragma unroll
        for (int j = 0; j < 8; j++)
            #pragma unroll
            for (int k = 0; k < 4; k++) sc[j][k] = 0.f;

        #pragma unroll
        for (int kk = 0; kk < 4; kk++) {
            uint32_t aH[4], aL[4];
            ldsm4(aH, aQH + kk * 32u);
            ldsm4(aL, aQL + kk * 32u);
            #pragma unroll
            for (int j = 0; j < 4; j++) {
                uint32_t bH[4], bL[4];
                ldsm4(bH, bKH + (uint32_t)j * 16u * LDB + kk * 32u);
                ldsm4(bL, bKL + (uint32_t)j * 16u * LDB + kk * 32u);
                mma16816(sc[2*j],   aH, bH[0], bH[1]);
                mma16816(sc[2*j+1], aH, bH[2], bH[3]);
                mma16816(sc[2*j],   aH, bL[0], bL[1]);
                mma16816(sc[2*j+1], aH, bL[2], bL[3]);
                mma16816(sc[2*j],   aL, bH[0], bH[1]);
                mma16816(sc[2*j+1], aL, bH[2], bH[3]);
            }
        }

        // ---- online softmax (base-2). rows: g=lane>>2 and g+8 ----
        float mx0 = -INFINITY, mx1 = -INFINITY;
        #pragma unroll
        for (int j = 0; j < 8; j++) {
            mx0 = fmaxf(mx0, fmaxf(sc[j][0], sc[j][1]));
            mx1 = fmaxf(mx1, fmaxf(sc[j][2], sc[j][3]));
        }
        mx0 = fmaxf(mx0, __shfl_xor_sync(0xffffffffu, mx0, 1));
        mx0 = fmaxf(mx0, __shfl_xor_sync(0xffffffffu, mx0, 2));
        mx1 = fmaxf(mx1, __shfl_xor_sync(0xffffffffu, mx1, 1));
        mx1 = fmaxf(mx1, __shfl_xor_sync(0xffffffffu, mx1, 2));
        const float mn0 = fmaxf(m0r, mx0);
        const float mn1 = fmaxf(m1r, mx1);
        const float al0 = ex2f(m0r - mn0);
        const float al1 = ex2f(m1r - mn1);
        m0r = mn0; m1r = mn1;

        float s0 = 0.f, s1 = 0.f;
        uint32_t pH[4][4], pL[4][4];
        #pragma unroll
        for (int kk = 0; kk < 4; kk++) {
            float p00 = ex2f(sc[2*kk][0]   - mn0), p01 = ex2f(sc[2*kk][1]   - mn0);
            float p10 = ex2f(sc[2*kk][2]   - mn1), p11 = ex2f(sc[2*kk][3]   - mn1);
            float q00 = ex2f(sc[2*kk+1][0] - mn0), q01 = ex2f(sc[2*kk+1][1] - mn0);
            float q10 = ex2f(sc[2*kk+1][2] - mn1), q11 = ex2f(sc[2*kk+1][3] - mn1);
            s0 += p00 + p01 + q00 + q01;
            s1 += p10 + p11 + q10 + q11;
            pH[kk][0] = bf2(p00, p01);  pL[kk][0] = lo_res(pH[kk][0], p00, p01);
            pH[kk][1] = bf2(p10, p11);  pL[kk][1] = lo_res(pH[kk][1], p10, p11);
            pH[kk][2] = bf2(q00, q01);  pL[kk][2] = lo_res(pH[kk][2], q00, q01);
            pH[kk][3] = bf2(q10, q11);  pL[kk][3] = lo_res(pH[kk][3], q10, q11);
        }
        s0 += __shfl_xor_sync(0xffffffffu, s0, 1);
        s0 += __shfl_xor_sync(0xffffffffu, s0, 2);
        s1 += __shfl_xor_sync(0xffffffffu, s1, 1);
        s1 += __shfl_xor_sync(0xffffffffu, s1, 2);
        l0r = l0r * al0 + s0;
        l1r = l1r * al1 + s1;

        #pragma unroll
        for (int j = 0; j < 8; j++) {
            oc[j][0] *= al0; oc[j][1] *= al0;
            oc[j][2] *= al1; oc[j][3] *= al1;
        }

        // ---- O += P V (3-term split) ----
        #pragma unroll
        for (int kk = 0; kk < 4; kk++) {
            #pragma unroll
            for (int j = 0; j < 4; j++) {
                uint32_t vH[4], vL[4];
                ldsm4(vH, bVH + (uint32_t)j * 16u * LDB + kk * 32u);
                ldsm4(vL, bVL + (uint32_t)j * 16u * LDB + kk * 32u);
                mma16816(oc[2*j],   pH[kk], vH[0], vH[1]);
                mma16816(oc[2*j+1], pH[kk], vH[2], vH[3]);
                mma16816(oc[2*j],   pH[kk], vL[0], vL[1]);
                mma16816(oc[2*j+1], pH[kk], vL[2], vL[3]);
                mma16816(oc[2*j],   pL[kk], vH[0], vH[1]);
                mma16816(oc[2*j+1], pL[kk], vH[2], vH[3]);
            }
        }
        __syncthreads();
    }

    // ---- finalize ----
    const float inv0 = 1.f / l0r;
    const float inv1 = 1.f / l1r;
    const int g  = lane >> 2;
    const int tg = lane & 3;
    float* r0p = Op + (size_t)(q0 + m0 + g)     * HD;
    float* r1p = Op + (size_t)(q0 + m0 + g + 8) * HD;
    #pragma unroll
    for (int j = 0; j < 8; j++) {
        float2 v0 = make_float2(oc[j][0] * inv0, oc[j][1] * inv0);
        float2 v1 = make_float2(oc[j][2] * inv1, oc[j][3] * inv1);
        *(float2*)(r0p + 8*j + 2*tg) = v0;
        *(float2*)(r1p + 8*j + 2*tg) = v1;
    }
}

// ---------------------------------------------------------------------------
// Kernel 3: out = O @ Wo^T + bo + x (SIMT fp32 GEMM, unchanged).
// ---------------------------------------------------------------------------
__global__ __launch_bounds__(256) void out_proj_kernel(
    const float* __restrict__ x,
    const float* __restrict__ Wo, const float* __restrict__ bo,
    float* __restrict__ out)
{
    __shared__ float As[8][128];
    __shared__ float Bs[8][128];

    const int t   = threadIdx.x;
    const int tr  = t >> 4;
    const int tc  = t & 15;
    const int bm0 = blockIdx.x * 128;
    const int bn0 = blockIdx.y * 128;
    const int lrow = t >> 1;
    const int lc4  = (t & 1) * 4;

    const int nrowA = bm0 + lrow;
    const int bA = nrowA >> 12;
    const int sA = nrowA & (SEQ - 1);

    float acc[8][8];
    #pragma unroll
    for (int i = 0; i < 8; i++)
        #pragma unroll
        for (int j = 0; j < 8; j++) acc[i][j] = 0.f;

    for (int k0 = 0; k0 < EMB; k0 += 8) {
        const int e = k0 + lc4;
        const int h = e >> 6, d = e & 63;
        float4 av  = *(const float4*)(g_O + ((size_t)(bA*NH + h)*SEQ + sA)*HD + d);
        float4 bv4 = *(const float4*)(Wo + (size_t)(bn0 + lrow) * EMB + k0 + lc4);
        As[lc4+0][lrow] = av.x;  As[lc4+1][lrow] = av.y;
        As[lc4+2][lrow] = av.z;  As[lc4+3][lrow] = av.w;
        Bs[lc4+0][lrow] = bv4.x; Bs[lc4+1][lrow] = bv4.y;
        Bs[lc4+2][lrow] = bv4.z; Bs[lc4+3][lrow] = bv4.w;
        __syncthreads();

        #pragma unroll
        for (int kk = 0; kk < 8; kk++) {
            float4 a0 = *(const float4*)&As[kk][tr*8];
            float4 a1 = *(const float4*)&As[kk][tr*8 + 4];
            float4 b0 = *(const float4*)&Bs[kk][tc*8];
            float4 b1 = *(const float4*)&Bs[kk][tc*8 + 4];
            float ar[8] = {a0.x,a0.y,a0.z,a0.w,a1.x,a1.y,a1.z,a1.w};
            float br[8] = {b0.x,b0.y,b0.z,b0.w,b1.x,b1.y,b1.z,b1.w};
            #pragma unroll
            for (int m = 0; m < 8; m++)
                #pragma unroll
                for (int n = 0; n < 8; n++)
                    acc[m][n] = fmaf(ar[m], br[n], acc[m][n]);
        }
        __syncthreads();
    }

    #pragma unroll
    for (int m = 0; m < 8; m++) {
        const int nrow = bm0 + tr*8 + m;
        #pragma unroll
        for (int n4 = 0; n4 < 8; n4 += 4) {
            const int j = bn0 + tc*8 + n4;
            float4 xr = *(const float4*)(x + (size_t)nrow*EMB + j);
            float4 v;
            v.x = acc[m][n4+0] + bo[j+0] + xr.x;
            v.y = acc[m][n4+1] + bo[j+1] + xr.y;
            v.z = acc[m][n4+2] + bo[j+2] + xr.z;
            v.w = acc[m][n4+3] + bo[j+3] + xr.w;
            *(float4*)(out + (size_t)nrow*EMB + j) = v;
        }
    }
}

// ---------------------------------------------------------------------------
extern "C" void kernel_launch(void* const* d_in, const int* in_sizes, int n_in,
                              void* d_out, int out_size)
{
    const float* x  = (const float*)d_in[0];
    const float* Wq = (const float*)d_in[1];
    const float* bq = (const float*)d_in[2];
    const float* Wk = (const float*)d_in[3];
    const float* bk = (const float*)d_in[4];
    const float* Wv = (const float*)d_in[5];
    const float* bv = (const float*)d_in[6];
    const float* Wo = (const float*)d_in[7];
    const float* bo = (const float*)d_in[8];
    float* out = (float*)d_out;

    cudaFuncSetAttribute(flash_mma,
                         cudaFuncAttributeMaxDynamicSharedMemorySize, SMEM_FLASH);

    proj_qkv_kernel<<<dim3(NROWS/128, EMB/128, 3), 256>>>(x, Wq, bq, Wk, bk, Wv, bv);
    flash_mma<<<dim3(SEQ/BQ, NB*NH), 256, SMEM_FLASH>>>();
    out_proj_kernel<<<dim3(NROWS/128, EMB/128), 256>>>(x, Wo, bo, out);
}

// round 6
// speedup vs baseline: 3.2625x; 1.8909x over previous
#include <cuda_runtime.h>
#include <cuda_bf16.h>
#include <math.h>
#include <stdint.h>

#define NB   2
#define SEQ  4096
#define EMB  512
#define NH   8
#define HD   64
#define NROWS (NB*SEQ)   // 8192

__device__ float g_Q[NB*NH*SEQ*HD];
__device__ float g_K[NB*NH*SEQ*HD];
__device__ float g_V[NB*NH*SEQ*HD];
__device__ float g_O[NB*NH*SEQ*HD];

// ============================ helpers ============================
static __device__ __forceinline__ uint32_t smem_u32(const void* p) {
    uint32_t a;
    asm("{ .reg .u64 t; cvta.to.shared.u64 t, %1; cvt.u32.u64 %0, t; }"
        : "=r"(a) : "l"(p));
    return a;
}
static __device__ __forceinline__ float ex2f(float x) {
    float r;
    asm("ex2.approx.f32 %0, %1;" : "=f"(r) : "f"(x));
    return r;
}
static __device__ __forceinline__ uint32_t bf2(float a, float b) {
    __nv_bfloat162 h = __floats2bfloat162_rn(a, b);
    return *reinterpret_cast<uint32_t*>(&h);
}
static __device__ __forceinline__ uint32_t lo_res(uint32_t h, float a, float b) {
    float ra = a - __uint_as_float(h << 16);
    float rb = b - __uint_as_float(h & 0xffff0000u);
    return bf2(ra, rb);
}
static __device__ __forceinline__ void ldsm4(uint32_t r[4], uint32_t addr) {
    asm volatile("ldmatrix.sync.aligned.m8n8.x4.shared.b16 {%0,%1,%2,%3}, [%4];"
                 : "=r"(r[0]), "=r"(r[1]), "=r"(r[2]), "=r"(r[3]) : "r"(addr));
}
static __device__ __forceinline__ void ldsm4t(uint32_t r[4], uint32_t addr) {
    asm volatile("ldmatrix.sync.aligned.m8n8.x4.trans.shared.b16 {%0,%1,%2,%3}, [%4];"
                 : "=r"(r[0]), "=r"(r[1]), "=r"(r[2]), "=r"(r[3]) : "r"(addr));
}
static __device__ __forceinline__ void mma16816(float c[4], const uint32_t a[4],
                                                uint32_t b0, uint32_t b1) {
    asm volatile(
        "mma.sync.aligned.m16n8k16.row.col.f32.bf16.bf16.f32 "
        "{%0,%1,%2,%3}, {%4,%5,%6,%7}, {%8,%9}, {%0,%1,%2,%3};"
        : "+f"(c[0]), "+f"(c[1]), "+f"(c[2]), "+f"(c[3])
        : "r"(a[0]), "r"(a[1]), "r"(a[2]), "r"(a[3]), "r"(b0), "r"(b1));
}
// pack fp32x4 -> hi/lo bf16x2 pairs and store as uint2 into two tiles
static __device__ __forceinline__ void st_hilo(char* smem, uint32_t offH, uint32_t offL,
                                               uint32_t byteoff, float4 v) {
    uint32_t h0 = bf2(v.x, v.y), h1 = bf2(v.z, v.w);
    uint32_t l0 = lo_res(h0, v.x, v.y), l1 = lo_res(h1, v.z, v.w);
    *(uint2*)(smem + offH + byteoff) = make_uint2(h0, h1);
    *(uint2*)(smem + offL + byteoff) = make_uint2(l0, l1);
}

#define LDB  144           // 64+8 bf16 elems per row, bytes

// ============================ flash smem ============================
#define BQ   256
#define BKV  64
#define FQ_H 0
#define FQ_L (FQ_H + BQ*LDB)     // 36864
#define FK_H (FQ_L + BQ*LDB)     // 73728
#define FK_L (FK_H + BKV*LDB)    // 82944
#define FV_H (FK_L + BKV*LDB)    // 92160
#define FV_L (FV_H + BKV*LDB)    // 101376
#define SMEM_FLASH (FV_L + BKV*LDB)  // 110592

// ============================ proj smem ============================
#define PA_H 0
#define PA_L (PA_H + 128*LDB)    // 18432
#define PB_H (PA_L + 128*LDB)    // 36864
#define PB_L (PB_H + 128*LDB)    // 55296
#define SMEM_PROJ (PB_L + 128*LDB)  // 73728

// ---------------------------------------------------------------------------
// Kernel 1: QKV projection, split-bf16 mma. CTA 128x128, warp 32x64, K=512.
// grid = (64, 4, 3)
// ---------------------------------------------------------------------------
__global__ void __launch_bounds__(256, 1) proj_qkv_mma(
    const float* __restrict__ x,
    const float* __restrict__ Wq, const float* __restrict__ bq,
    const float* __restrict__ Wk, const float* __restrict__ bk,
    const float* __restrict__ Wv, const float* __restrict__ bv)
{
    extern __shared__ char smem[];
    const uint32_t sb = smem_u32(smem);

    const float* W; const float* bias; float* outp;
    if (blockIdx.z == 0)      { W = Wq; bias = bq; outp = g_Q; }
    else if (blockIdx.z == 1) { W = Wk; bias = bk; outp = g_K; }
    else                      { W = Wv; bias = bv; outp = g_V; }

    const int t    = threadIdx.x;
    const int wid  = t >> 5;
    const int lane = t & 31;
    const int bm0  = blockIdx.x * 128;
    const int bn0  = blockIdx.y * 128;
    const int wm   = (wid & 3) * 32;
    const int wn   = (wid >> 2) * 64;

    const uint32_t aoff = (uint32_t)(wm + (lane & 15)) * LDB + ((uint32_t)(lane >> 4) << 4);
    const uint32_t boff = (uint32_t)(wn + (lane & 7) + ((lane >> 4) << 3)) * LDB
                        + ((uint32_t)((lane >> 3) & 1) << 4);
    const uint32_t aAH = sb + PA_H + aoff, aAL = sb + PA_L + aoff;
    const uint32_t bBH = sb + PB_H + boff, bBL = sb + PB_L + boff;

    float acc[2][8][4];
    #pragma unroll
    for (int m = 0; m < 2; m++)
        #pragma unroll
        for (int b = 0; b < 8; b++)
            #pragma unroll
            for (int k = 0; k < 4; k++) acc[m][b][k] = 0.f;

    #pragma unroll 1
    for (int c = 0; c < 8; c++) {
        const int k0 = c * 64;
        #pragma unroll
        for (int i = 0; i < 8; i++) {
            int j = t + 256 * i;
            int r = j >> 4, c4 = (j & 15) * 4;
            uint32_t off = (uint32_t)r * LDB + (uint32_t)c4 * 2u;
            float4 va = *(const float4*)(x + (size_t)(bm0 + r) * EMB + k0 + c4);
            st_hilo(smem, PA_H, PA_L, off, va);
            float4 vb = *(const float4*)(W + (size_t)(bn0 + r) * EMB + k0 + c4);
            st_hilo(smem, PB_H, PB_L, off, vb);
        }
        __syncthreads();

        #pragma unroll
        for (int kk = 0; kk < 4; kk++) {
            uint32_t aH[2][4], aL[2][4];
            ldsm4(aH[0], aAH + kk * 32u);
            ldsm4(aL[0], aAL + kk * 32u);
            ldsm4(aH[1], aAH + 16u * LDB + kk * 32u);
            ldsm4(aL[1], aAL + 16u * LDB + kk * 32u);
            #pragma unroll
            for (int j = 0; j < 4; j++) {
                uint32_t bH[4], bL[4];
                ldsm4(bH, bBH + (uint32_t)j * (16u * LDB) + kk * 32u);
                ldsm4(bL, bBL + (uint32_t)j * (16u * LDB) + kk * 32u);
                #pragma unroll
                for (int m = 0; m < 2; m++) {
                    mma16816(acc[m][2*j],   aH[m], bH[0], bH[1]);
                    mma16816(acc[m][2*j+1], aH[m], bH[2], bH[3]);
                    mma16816(acc[m][2*j],   aH[m], bL[0], bL[1]);
                    mma16816(acc[m][2*j+1], aH[m], bL[2], bL[3]);
                    mma16816(acc[m][2*j],   aL[m], bH[0], bH[1]);
                    mma16816(acc[m][2*j+1], aL[m], bH[2], bH[3]);
                }
            }
        }
        __syncthreads();
    }

    // epilogue: +bias, scatter to [B,H,S,D]
    const int g  = lane >> 2;
    const int tg = lane & 3;
    #pragma unroll
    for (int m = 0; m < 2; m++) {
        #pragma unroll
        for (int b = 0; b < 8; b++) {
            const int col = bn0 + wn + b * 8 + tg * 2;
            const int h = col >> 6, d = col & 63;
            const float b0v = bias[col], b1v = bias[col + 1];
            #pragma unroll
            for (int rr = 0; rr < 2; rr++) {
                const int row = bm0 + wm + m * 16 + g + rr * 8;
                const int bb = row >> 12, s = row & (SEQ - 1);
                float2 v = make_float2(acc[m][b][2*rr] + b0v, acc[m][b][2*rr+1] + b1v);
                *(float2*)(outp + ((size_t)(bb * NH + h) * SEQ + s) * HD + d) = v;
            }
        }
    }
}

// ---------------------------------------------------------------------------
// Kernel 2: flash attention, split-bf16 mma. BQ=256 (8 warps x 32 rows),
// BKV=64, V via ldmatrix.trans. grid = (SEQ/256, NB*NH).
// ---------------------------------------------------------------------------
__global__ void __launch_bounds__(256, 1) flash_mma()
{
    extern __shared__ char smem[];
    const uint32_t sb = smem_u32(smem);

    const int t    = threadIdx.x;
    const int wid  = t >> 5;
    const int lane = t & 31;
    const int bh   = blockIdx.y;
    const int q0   = blockIdx.x * BQ;

    const float* Qp = g_Q + (size_t)bh * SEQ * HD;
    const float* Kp = g_K + (size_t)bh * SEQ * HD;
    const float* Vp = g_V + (size_t)bh * SEQ * HD;
    float*       Op = g_O + (size_t)bh * SEQ * HD;

    // ---- stage Q (scaled by 0.125*log2e), hi/lo ----
    const float qscale = 0.125f * 1.4426950408889634f;
    #pragma unroll
    for (int i = 0; i < 16; i++) {
        int j = t + 256 * i;
        int r = j >> 4, c4 = (j & 15) * 4;
        float4 v = *(const float4*)(Qp + (size_t)(q0 + r) * HD + c4);
        v.x *= qscale; v.y *= qscale; v.z *= qscale; v.w *= qscale;
        st_hilo(smem, FQ_H, FQ_L, (uint32_t)r * LDB + (uint32_t)c4 * 2u, v);
    }

    const int wm = wid * 32;
    const uint32_t aoff = (uint32_t)(wm + (lane & 15)) * LDB + ((uint32_t)(lane >> 4) << 4);
    const uint32_t koff = (uint32_t)((lane & 7) + ((lane >> 4) << 3)) * LDB
                        + ((uint32_t)((lane >> 3) & 1) << 4);
    const uint32_t voff = (uint32_t)((lane & 7) + (((lane >> 3) & 1) << 3)) * LDB
                        + ((uint32_t)(lane >> 4) << 4);
    const uint32_t aQH = sb + FQ_H + aoff, aQL = sb + FQ_L + aoff;
    const uint32_t bKH = sb + FK_H + koff, bKL = sb + FK_L + koff;
    const uint32_t bVH = sb + FV_H + voff, bVL = sb + FV_L + voff;

    float mr[2][2], lr[2][2];
    #pragma unroll
    for (int m = 0; m < 2; m++) { mr[m][0] = mr[m][1] = -INFINITY; lr[m][0] = lr[m][1] = 0.f; }
    float oc[2][8][4];
    #pragma unroll
    for (int m = 0; m < 2; m++)
        #pragma unroll
        for (int b = 0; b < 8; b++)
            #pragma unroll
            for (int k = 0; k < 4; k++) oc[m][b][k] = 0.f;

    #pragma unroll 1
    for (int kv0 = 0; kv0 < SEQ; kv0 += BKV) {
        // ---- stage K and V (both row-major [kv][d], hi/lo) ----
        #pragma unroll
        for (int i = 0; i < 4; i++) {
            int j = t + 256 * i;
            int r = j >> 4, c4 = (j & 15) * 4;
            uint32_t off = (uint32_t)r * LDB + (uint32_t)c4 * 2u;
            float4 vk = *(const float4*)(Kp + (size_t)(kv0 + r) * HD + c4);
            st_hilo(smem, FK_H, FK_L, off, vk);
            float4 vv = *(const float4*)(Vp + (size_t)(kv0 + r) * HD + c4);
            st_hilo(smem, FV_H, FV_L, off, vv);
        }
        __syncthreads();

        // ---- S = Q K^T ----
        float sc[2][8][4];
        #pragma unroll
        for (int m = 0; m < 2; m++)
            #pragma unroll
            for (int b = 0; b < 8; b++)
                #pragma unroll
                for (int k = 0; k < 4; k++) sc[m][b][k] = 0.f;

        #pragma unroll
        for (int kk = 0; kk < 4; kk++) {
            uint32_t aH[2][4], aL[2][4];
            ldsm4(aH[0], aQH + kk * 32u);
            ldsm4(aL[0], aQL + kk * 32u);
            ldsm4(aH[1], aQH + 16u * LDB + kk * 32u);
            ldsm4(aL[1], aQL + 16u * LDB + kk * 32u);
            #pragma unroll
            for (int j = 0; j < 4; j++) {
                uint32_t bH[4], bL[4];
                ldsm4(bH, bKH + (uint32_t)j * (16u * LDB) + kk * 32u);
                ldsm4(bL, bKL + (uint32_t)j * (16u * LDB) + kk * 32u);
                #pragma unroll
                for (int m = 0; m < 2; m++) {
                    mma16816(sc[m][2*j],   aH[m], bH[0], bH[1]);
                    mma16816(sc[m][2*j+1], aH[m], bH[2], bH[3]);
                    mma16816(sc[m][2*j],   aH[m], bL[0], bL[1]);
                    mma16816(sc[m][2*j+1], aH[m], bL[2], bL[3]);
                    mma16816(sc[m][2*j],   aL[m], bH[0], bH[1]);
                    mma16816(sc[m][2*j+1], aL[m], bH[2], bH[3]);
                }
            }
        }

        // ---- online softmax (base-2) + P fragments ----
        uint32_t pH[2][4][4], pL[2][4][4];
        #pragma unroll
        for (int m = 0; m < 2; m++) {
            float mx0 = -INFINITY, mx1 = -INFINITY;
            #pragma unroll
            for (int b = 0; b < 8; b++) {
                mx0 = fmaxf(mx0, fmaxf(sc[m][b][0], sc[m][b][1]));
                mx1 = fmaxf(mx1, fmaxf(sc[m][b][2], sc[m][b][3]));
            }
            mx0 = fmaxf(mx0, __shfl_xor_sync(0xffffffffu, mx0, 1));
            mx0 = fmaxf(mx0, __shfl_xor_sync(0xffffffffu, mx0, 2));
            mx1 = fmaxf(mx1, __shfl_xor_sync(0xffffffffu, mx1, 1));
            mx1 = fmaxf(mx1, __shfl_xor_sync(0xffffffffu, mx1, 2));
            const float mn0 = fmaxf(mr[m][0], mx0);
            const float mn1 = fmaxf(mr[m][1], mx1);
            const float al0 = ex2f(mr[m][0] - mn0);
            const float al1 = ex2f(mr[m][1] - mn1);
            mr[m][0] = mn0; mr[m][1] = mn1;

            float s0 = 0.f, s1 = 0.f;
            #pragma unroll
            for (int kk = 0; kk < 4; kk++) {
                float p00 = ex2f(sc[m][2*kk][0]   - mn0), p01 = ex2f(sc[m][2*kk][1]   - mn0);
                float p02 = ex2f(sc[m][2*kk][2]   - mn1), p03 = ex2f(sc[m][2*kk][3]   - mn1);
                float q00 = ex2f(sc[m][2*kk+1][0] - mn0), q01 = ex2f(sc[m][2*kk+1][1] - mn0);
                float q02 = ex2f(sc[m][2*kk+1][2] - mn1), q03 = ex2f(sc[m][2*kk+1][3] - mn1);
                s0 += p00 + p01 + q00 + q01;
                s1 += p02 + p03 + q02 + q03;
                pH[m][kk][0] = bf2(p00, p01);  pL[m][kk][0] = lo_res(pH[m][kk][0], p00, p01);
                pH[m][kk][1] = bf2(p02, p03);  pL[m][kk][1] = lo_res(pH[m][kk][1], p02, p03);
                pH[m][kk][2] = bf2(q00, q01);  pL[m][kk][2] = lo_res(pH[m][kk][2], q00, q01);
                pH[m][kk][3] = bf2(q02, q03);  pL[m][kk][3] = lo_res(pH[m][kk][3], q02, q03);
            }
            s0 += __shfl_xor_sync(0xffffffffu, s0, 1);
            s0 += __shfl_xor_sync(0xffffffffu, s0, 2);
            s1 += __shfl_xor_sync(0xffffffffu, s1, 1);
            s1 += __shfl_xor_sync(0xffffffffu, s1, 2);
            lr[m][0] = lr[m][0] * al0 + s0;
            lr[m][1] = lr[m][1] * al1 + s1;
            #pragma unroll
            for (int b = 0; b < 8; b++) {
                oc[m][b][0] *= al0; oc[m][b][1] *= al0;
                oc[m][b][2] *= al1; oc[m][b][3] *= al1;
            }
        }

        // ---- O += P V (V via ldmatrix.trans) ----
        #pragma unroll
        for (int kk = 0; kk < 4; kk++) {
            #pragma unroll
            for (int j = 0; j < 4; j++) {
                uint32_t vH[4], vL[4];
                ldsm4t(vH, bVH + (uint32_t)kk * (16u * LDB) + (uint32_t)j * 32u);
                ldsm4t(vL, bVL + (uint32_t)kk * (16u * LDB) + (uint32_t)j * 32u);
                #pragma unroll
                for (int m = 0; m < 2; m++) {
                    mma16816(oc[m][2*j],   pH[m][kk], vH[0], vH[1]);
                    mma16816(oc[m][2*j+1], pH[m][kk], vH[2], vH[3]);
                    mma16816(oc[m][2*j],   pH[m][kk], vL[0], vL[1]);
                    mma16816(oc[m][2*j+1], pH[m][kk], vL[2], vL[3]);
                    mma16816(oc[m][2*j],   pL[m][kk], vH[0], vH[1]);
                    mma16816(oc[m][2*j+1], pL[m][kk], vH[2], vH[3]);
                }
            }
        }
        __syncthreads();
    }

    // ---- finalize ----
    const int g  = lane >> 2;
    const int tg = lane & 3;
    #pragma unroll
    for (int m = 0; m < 2; m++) {
        const float inv0 = 1.f / lr[m][0];
        const float inv1 = 1.f / lr[m][1];
        float* r0p = Op + (size_t)(q0 + wm + m * 16 + g)     * HD;
        float* r1p = Op + (size_t)(q0 + wm + m * 16 + g + 8) * HD;
        #pragma unroll
        for (int b = 0; b < 8; b++) {
            *(float2*)(r0p + b * 8 + tg * 2) = make_float2(oc[m][b][0] * inv0, oc[m][b][1] * inv0);
            *(float2*)(r1p + b * 8 + tg * 2) = make_float2(oc[m][b][2] * inv1, oc[m][b][3] * inv1);
        }
    }
}

// ---------------------------------------------------------------------------
// Kernel 3: out = O @ Wo^T + bo + x, split-bf16 mma. grid = (64, 4).
// ---------------------------------------------------------------------------
__global__ void __launch_bounds__(256, 1) out_proj_mma(
    const float* __restrict__ x,
    const float* __restrict__ Wo, const float* __restrict__ bo,
    float* __restrict__ out)
{
    extern __shared__ char smem[];
    const uint32_t sb = smem_u32(smem);

    const int t    = threadIdx.x;
    const int wid  = t >> 5;
    const int lane = t & 31;
    const int bm0  = blockIdx.x * 128;
    const int bn0  = blockIdx.y * 128;
    const int wm   = (wid & 3) * 32;
    const int wn   = (wid >> 2) * 64;

    const uint32_t aoff = (uint32_t)(wm + (lane & 15)) * LDB + ((uint32_t)(lane >> 4) << 4);
    const uint32_t boff = (uint32_t)(wn + (lane & 7) + ((lane >> 4) << 3)) * LDB
                        + ((uint32_t)((lane >> 3) & 1) << 4);
    const uint32_t aAH = sb + PA_H + aoff, aAL = sb + PA_L + aoff;
    const uint32_t bBH = sb + PB_H + boff, bBL = sb + PB_L + boff;

    float acc[2][8][4];
    #pragma unroll
    for (int m = 0; m < 2; m++)
        #pragma unroll
        for (int b = 0; b < 8; b++)
            #pragma unroll
            for (int k = 0; k < 4; k++) acc[m][b][k] = 0.f;

    #pragma unroll 1
    for (int c = 0; c < 8; c++) {
        const int k0 = c * 64;
        #pragma unroll
        for (int i = 0; i < 8; i++) {
            int j = t + 256 * i;
            int r = j >> 4, c4 = (j & 15) * 4;
            uint32_t off = (uint32_t)r * LDB + (uint32_t)c4 * 2u;
            // gather A from g_O [B,H,S,D]: head = chunk index, d = c4
            const int nrow = bm0 + r;
            const int bb = nrow >> 12, s = nrow & (SEQ - 1);
            float4 va = *(const float4*)(g_O + ((size_t)(bb * NH + c) * SEQ + s) * HD + c4);
            st_hilo(smem, PA_H, PA_L, off, va);
            float4 vb = *(const float4*)(Wo + (size_t)(bn0 + r) * EMB + k0 + c4);
            st_hilo(smem, PB_H, PB_L, off, vb);
        }
        __syncthreads();

        #pragma unroll
        for (int kk = 0; kk < 4; kk++) {
            uint32_t aH[2][4], aL[2][4];
            ldsm4(aH[0], aAH + kk * 32u);
            ldsm4(aL[0], aAL + kk * 32u);
            ldsm4(aH[1], aAH + 16u * LDB + kk * 32u);
            ldsm4(aL[1], aAL + 16u * LDB + kk * 32u);
            #pragma unroll
            for (int j = 0; j < 4; j++) {
                uint32_t bH[4], bL[4];
                ldsm4(bH, bBH + (uint32_t)j * (16u * LDB) + kk * 32u);
                ldsm4(bL, bBL + (uint32_t)j * (16u * LDB) + kk * 32u);
                #pragma unroll
                for (int m = 0; m < 2; m++) {
                    mma16816(acc[m][2*j],   aH[m], bH[0], bH[1]);
                    mma16816(acc[m][2*j+1], aH[m], bH[2], bH[3]);
                    mma16816(acc[m][2*j],   aH[m], bL[0], bL[1]);
                    mma16816(acc[m][2*j+1], aH[m], bL[2], bL[3]);
                    mma16816(acc[m][2*j],   aL[m], bH[0], bH[1]);
                    mma16816(acc[m][2*j+1], aL[m], bH[2], bH[3]);
                }
            }
        }
        __syncthreads();
    }

    // epilogue: + bo + residual x
    const int g  = lane >> 2;
    const int tg = lane & 3;
    #pragma unroll
    for (int m = 0; m < 2; m++) {
        #pragma unroll
        for (int b = 0; b < 8; b++) {
            const int col = bn0 + wn + b * 8 + tg * 2;
            const float b0v = bo[col], b1v = bo[col + 1];
            #pragma unroll
            for (int rr = 0; rr < 2; rr++) {
                const int row = bm0 + wm + m * 16 + g + rr * 8;
                float2 xr = *(const float2*)(x + (size_t)row * EMB + col);
                float2 v = make_float2(acc[m][b][2*rr] + b0v + xr.x,
                                       acc[m][b][2*rr+1] + b1v + xr.y);
                *(float2*)(out + (size_t)row * EMB + col) = v;
            }
        }
    }
}

// ---------------------------------------------------------------------------
extern "C" void kernel_launch(void* const* d_in, const int* in_sizes, int n_in,
                              void* d_out, int out_size)
{
    const float* x  = (const float*)d_in[0];
    const float* Wq = (const float*)d_in[1];
    const float* bq = (const float*)d_in[2];
    const float* Wk = (const float*)d_in[3];
    const float* bk = (const float*)d_in[4];
    const float* Wv = (const float*)d_in[5];
    const float* bv = (const float*)d_in[6];
    const float* Wo = (const float*)d_in[7];
    const float* bo = (const float*)d_in[8];
    float* out = (float*)d_out;

    cudaFuncSetAttribute(proj_qkv_mma,
                         cudaFuncAttributeMaxDynamicSharedMemorySize, SMEM_PROJ);
    cudaFuncSetAttribute(out_proj_mma,
                         cudaFuncAttributeMaxDynamicSharedMemorySize, SMEM_PROJ);
    cudaFuncSetAttribute(flash_mma,
                         cudaFuncAttributeMaxDynamicSharedMemorySize, SMEM_FLASH);

    proj_qkv_mma<<<dim3(NROWS/128, EMB/128, 3), 256, SMEM_PROJ>>>(x, Wq, bq, Wk, bk, Wv, bv);
    flash_mma<<<dim3(SEQ/BQ, NB*NH), 256, SMEM_FLASH>>>();
    out_proj_mma<<<dim3(NROWS/128, EMB/128), 256, SMEM_PROJ>>>(x, Wo, bo, out);
}

// round 7
// speedup vs baseline: 3.3448x; 1.0252x over previous
#include <cuda_runtime.h>
#include <cuda_bf16.h>
#include <math.h>
#include <stdint.h>

#define NB   2
#define SEQ  4096
#define EMB  512
#define NH   8
#define HD   64
#define NROWS (NB*SEQ)   // 8192

// bf16 hi/lo plane scratch (allocation-free)
__device__ __nv_bfloat16 g_xh[NROWS*EMB], g_xl[NROWS*EMB];
__device__ __nv_bfloat16 g_Wh[4*EMB*EMB], g_Wl[4*EMB*EMB];
__device__ __nv_bfloat16 g_Qh[NB*NH*SEQ*HD], g_Ql[NB*NH*SEQ*HD];
__device__ __nv_bfloat16 g_Kh[NB*NH*SEQ*HD], g_Kl[NB*NH*SEQ*HD];
__device__ __nv_bfloat16 g_Vh[NB*NH*SEQ*HD], g_Vl[NB*NH*SEQ*HD];
__device__ __nv_bfloat16 g_Oh[NB*NH*SEQ*HD], g_Ol[NB*NH*SEQ*HD];

// ============================ helpers ============================
static __device__ __forceinline__ uint32_t smem_u32(const void* p) {
    uint32_t a;
    asm("{ .reg .u64 t; cvta.to.shared.u64 t, %1; cvt.u32.u64 %0, t; }"
        : "=r"(a) : "l"(p));
    return a;
}
static __device__ __forceinline__ float ex2f(float x) {
    float r;
    asm("ex2.approx.f32 %0, %1;" : "=f"(r) : "f"(x));
    return r;
}
static __device__ __forceinline__ uint32_t bf2(float a, float b) {
    __nv_bfloat162 h = __floats2bfloat162_rn(a, b);
    return *reinterpret_cast<uint32_t*>(&h);
}
static __device__ __forceinline__ uint32_t lo_res(uint32_t h, float a, float b) {
    float ra = a - __uint_as_float(h << 16);
    float rb = b - __uint_as_float(h & 0xffff0000u);
    return bf2(ra, rb);
}
static __device__ __forceinline__ void ldsm4(uint32_t r[4], uint32_t addr) {
    asm volatile("ldmatrix.sync.aligned.m8n8.x4.shared.b16 {%0,%1,%2,%3}, [%4];"
                 : "=r"(r[0]), "=r"(r[1]), "=r"(r[2]), "=r"(r[3]) : "r"(addr));
}
static __device__ __forceinline__ void ldsm4t(uint32_t r[4], uint32_t addr) {
    asm volatile("ldmatrix.sync.aligned.m8n8.x4.trans.shared.b16 {%0,%1,%2,%3}, [%4];"
                 : "=r"(r[0]), "=r"(r[1]), "=r"(r[2]), "=r"(r[3]) : "r"(addr));
}
static __device__ __forceinline__ void mma16816(float c[4], const uint32_t a[4],
                                                uint32_t b0, uint32_t b1) {
    asm volatile(
        "mma.sync.aligned.m16n8k16.row.col.f32.bf16.bf16.f32 "
        "{%0,%1,%2,%3}, {%4,%5,%6,%7}, {%8,%9}, {%0,%1,%2,%3};"
        : "+f"(c[0]), "+f"(c[1]), "+f"(c[2]), "+f"(c[3])
        : "r"(a[0]), "r"(a[1]), "r"(a[2]), "r"(a[3]), "r"(b0), "r"(b1));
}
#define CP16(dst, src) asm volatile("cp.async.cg.shared.global [%0], [%1], 16;" :: "r"(dst), "l"(src))
#define CP_COMMIT()    asm volatile("cp.async.commit_group;")
#define CP_WAIT1()     asm volatile("cp.async.wait_group 1;")

#define LDB  144           // 64+8 bf16 elems per row, bytes

// ---------------------------------------------------------------------------
// Kernel 0: split x and the 4 weight matrices into bf16 hi/lo planes.
// ---------------------------------------------------------------------------
__global__ void __launch_bounds__(256) convert_inputs(
    const float* __restrict__ x,
    const float* __restrict__ Wq, const float* __restrict__ Wk,
    const float* __restrict__ Wv, const float* __restrict__ Wo)
{
    const int NX4 = NROWS * EMB / 4;      // 1048576
    const int NW4 = EMB * EMB / 4;        // 65536
    int i4 = blockIdx.x * 256 + threadIdx.x;
    float4 v; uint2* dh; uint2* dl; int j;
    if (i4 < NX4) {
        v = ((const float4*)x)[i4];
        dh = (uint2*)g_xh; dl = (uint2*)g_xl; j = i4;
    } else {
        int r = i4 - NX4;
        int w = r / NW4;
        if (w >= 4) return;
        j = r - w * NW4;
        const float* W = (w == 0) ? Wq : (w == 1) ? Wk : (w == 2) ? Wv : Wo;
        v = ((const float4*)W)[j];
        dh = (uint2*)(g_Wh + (size_t)w * EMB * EMB);
        dl = (uint2*)(g_Wl + (size_t)w * EMB * EMB);
    }
    uint32_t h0 = bf2(v.x, v.y), h1 = bf2(v.z, v.w);
    uint32_t l0 = lo_res(h0, v.x, v.y), l1 = lo_res(h1, v.z, v.w);
    dh[j] = make_uint2(h0, h1);
    dl[j] = make_uint2(l0, l1);
}

// ============================ proj smem ============================
// per stage: A_H 0, A_L 18432, B_H 36864, B_L 55296 ; stage size 73728
#define P_AH 0
#define P_AL 18432
#define P_BH 36864
#define P_BL 55296
#define P_STG 73728
#define SMEM_PROJ (2*P_STG)   // 147456

// stage one k-chunk (A plane pair + B plane pair) via cp.async
static __device__ __forceinline__ void proj_stage(
    uint32_t sdst, const __nv_bfloat16* Ah, const __nv_bfloat16* Al,
    const __nv_bfloat16* Bh, const __nv_bfloat16* Bl,
    int t)
{
    #pragma unroll
    for (int i = 0; i < 16; i++) {
        int j = t + 256 * i;          // 0..4095
        int plane = j >> 10;          // 0..3
        int r  = (j >> 3) & 127;
        int c8 = j & 7;
        const __nv_bfloat16* src =
            (plane == 0) ? Ah : (plane == 1) ? Al : (plane == 2) ? Bh : Bl;
        uint32_t dst = sdst + (uint32_t)plane * 18432u
                     + (uint32_t)r * LDB + (uint32_t)c8 * 16u;
        CP16(dst, src + (size_t)r * EMB + c8 * 8);
    }
}

// ---------------------------------------------------------------------------
// Kernel 1: QKV projection, bf16 planes + cp.async pipeline.
// CTA 128x128, warp 32x64, K chunks of 64 (8 chunks). grid=(64,4,3).
// Epilogue writes Q/K/V hi/lo planes (Q pre-scaled by 0.125*log2e).
// ---------------------------------------------------------------------------
__global__ void __launch_bounds__(256, 1) proj_qkv_mma(
    const float* __restrict__ bq, const float* __restrict__ bk,
    const float* __restrict__ bv)
{
    extern __shared__ char smem[];
    const uint32_t sb = smem_u32(smem);

    const int z = blockIdx.z;
    const float* bias = (z == 0) ? bq : (z == 1) ? bk : bv;
    __nv_bfloat16* outH = (z == 0) ? g_Qh : (z == 1) ? g_Kh : g_Vh;
    __nv_bfloat16* outL = (z == 0) ? g_Ql : (z == 1) ? g_Kl : g_Vl;
    const __nv_bfloat16* WH = g_Wh + (size_t)z * EMB * EMB;
    const __nv_bfloat16* WL = g_Wl + (size_t)z * EMB * EMB;

    const int t    = threadIdx.x;
    const int wid  = t >> 5;
    const int lane = t & 31;
    const int bm0  = blockIdx.x * 128;
    const int bn0  = blockIdx.y * 128;
    const int wm   = (wid & 3) * 32;
    const int wn   = (wid >> 2) * 64;

    const uint32_t aoff = (uint32_t)(wm + (lane & 15)) * LDB + ((uint32_t)(lane >> 4) << 4);
    const uint32_t boff = (uint32_t)(wn + (lane & 7) + ((lane >> 4) << 3)) * LDB
                        + ((uint32_t)((lane >> 3) & 1) << 4);

    float acc[2][8][4];
    #pragma unroll
    for (int m = 0; m < 2; m++)
        #pragma unroll
        for (int b = 0; b < 8; b++)
            #pragma unroll
            for (int k = 0; k < 4; k++) acc[m][b][k] = 0.f;

    // prefetch chunk 0
    proj_stage(sb, g_xh + (size_t)bm0 * EMB, g_xl + (size_t)bm0 * EMB,
               WH + (size_t)bn0 * EMB, WL + (size_t)bn0 * EMB, t);
    CP_COMMIT();

    #pragma unroll 1
    for (int c = 0; c < 8; c++) {
        if (c < 7) {
            const int k1 = (c + 1) * 64;
            proj_stage(sb + ((c + 1) & 1) * P_STG,
                       g_xh + (size_t)bm0 * EMB + k1, g_xl + (size_t)bm0 * EMB + k1,
                       WH + (size_t)bn0 * EMB + k1, WL + (size_t)bn0 * EMB + k1, t);
        }
        CP_COMMIT();
        CP_WAIT1();
        __syncthreads();

        const uint32_t st = sb + (c & 1) * P_STG;
        const uint32_t aAH = st + P_AH + aoff, aAL = st + P_AL + aoff;
        const uint32_t bBH = st + P_BH + boff, bBL = st + P_BL + boff;

        #pragma unroll
        for (int kk = 0; kk < 4; kk++) {
            uint32_t aH[2][4], aL[2][4];
            ldsm4(aH[0], aAH + kk * 32u);
            ldsm4(aL[0], aAL + kk * 32u);
            ldsm4(aH[1], aAH + 16u * LDB + kk * 32u);
            ldsm4(aL[1], aAL + 16u * LDB + kk * 32u);
            #pragma unroll
            for (int j = 0; j < 4; j++) {
                uint32_t bH[4], bL[4];
                ldsm4(bH, bBH + (uint32_t)j * (16u * LDB) + kk * 32u);
                ldsm4(bL, bBL + (uint32_t)j * (16u * LDB) + kk * 32u);
                #pragma unroll
                for (int m = 0; m < 2; m++) {
                    mma16816(acc[m][2*j],   aH[m], bH[0], bH[1]);
                    mma16816(acc[m][2*j+1], aH[m], bH[2], bH[3]);
                    mma16816(acc[m][2*j],   aH[m], bL[0], bL[1]);
                    mma16816(acc[m][2*j+1], aH[m], bL[2], bL[3]);
                    mma16816(acc[m][2*j],   aL[m], bH[0], bH[1]);
                    mma16816(acc[m][2*j+1], aL[m], bH[2], bH[3]);
                }
            }
        }
        __syncthreads();
    }

    // epilogue: +bias, (Q: *qscale), split hi/lo, scatter to [B,H,S,D] planes
    const float qscale = (z == 0) ? 0.125f * 1.4426950408889634f : 1.0f;
    const int g  = lane >> 2;
    const int tg = lane & 3;
    #pragma unroll
    for (int m = 0; m < 2; m++) {
        #pragma unroll
        for (int b = 0; b < 8; b++) {
            const int col = bn0 + wn + b * 8 + tg * 2;
            const int h = col >> 6, d = col & 63;
            const float b0v = bias[col], b1v = bias[col + 1];
            #pragma unroll
            for (int rr = 0; rr < 2; rr++) {
                const int row = bm0 + wm + m * 16 + g + rr * 8;
                const int bb = row >> 12, s = row & (SEQ - 1);
                float v0 = (acc[m][b][2*rr]   + b0v) * qscale;
                float v1 = (acc[m][b][2*rr+1] + b1v) * qscale;
                uint32_t h0 = bf2(v0, v1);
                uint32_t l0 = lo_res(h0, v0, v1);
                size_t off = ((size_t)(bb * NH + h) * SEQ + s) * HD + d;
                *(uint32_t*)(outH + off) = h0;
                *(uint32_t*)(outL + off) = l0;
            }
        }
    }
}

// ============================ flash smem ============================
#define BQ   256
#define BKV  64
#define FQ_H 0
#define FQ_L (FQ_H + BQ*LDB)     // 36864
#define FKV  (FQ_L + BQ*LDB)     // 73728
// per stage: K_H 0, K_L 9216, V_H 18432, V_L 27648 ; stage size 36864
#define F_STG 36864
#define SMEM_FLASH (FKV + 2*F_STG)  // 147456

static __device__ __forceinline__ void flash_stage_kv(
    uint32_t sdst, const __nv_bfloat16* Kh, const __nv_bfloat16* Kl,
    const __nv_bfloat16* Vh, const __nv_bfloat16* Vl, int t)
{
    #pragma unroll
    for (int i = 0; i < 8; i++) {
        int j = t + 256 * i;          // 0..2047
        int plane = j >> 9;           // 0..3
        int r  = (j >> 3) & 63;
        int c8 = j & 7;
        const __nv_bfloat16* src =
            (plane == 0) ? Kh : (plane == 1) ? Kl : (plane == 2) ? Vh : Vl;
        uint32_t dst = sdst + (uint32_t)plane * 9216u
                     + (uint32_t)r * LDB + (uint32_t)c8 * 16u;
        CP16(dst, src + (size_t)r * HD + c8 * 8);
    }
}

// ---------------------------------------------------------------------------
// Kernel 2: flash attention, bf16 planes + cp.async double-buffered KV.
// BQ=256 (8 warps x 32 rows), BKV=64. grid = (SEQ/256, NB*NH).
// ---------------------------------------------------------------------------
__global__ void __launch_bounds__(256, 1) flash_mma()
{
    extern __shared__ char smem[];
    const uint32_t sb = smem_u32(smem);

    const int t    = threadIdx.x;
    const int wid  = t >> 5;
    const int lane = t & 31;
    const int bh   = blockIdx.y;
    const int q0   = blockIdx.x * BQ;

    const size_t base = (size_t)bh * SEQ * HD;
    const __nv_bfloat16* Qh = g_Qh + base;
    const __nv_bfloat16* Ql = g_Ql + base;
    const __nv_bfloat16* Kh = g_Kh + base;
    const __nv_bfloat16* Kl = g_Kl + base;
    const __nv_bfloat16* Vh = g_Vh + base;
    const __nv_bfloat16* Vl = g_Vl + base;

    // ---- stage Q (cp.async) + first KV tile, one group ----
    #pragma unroll
    for (int i = 0; i < 16; i++) {
        int j = t + 256 * i;          // 0..4095
        int plane = j >> 11;          // 0..1
        int r  = (j >> 3) & 255;
        int c8 = j & 7;
        const __nv_bfloat16* src = plane ? Ql : Qh;
        uint32_t dst = sb + (plane ? FQ_L : FQ_H)
                     + (uint32_t)r * LDB + (uint32_t)c8 * 16u;
        CP16(dst, src + (size_t)(q0 + r) * HD + c8 * 8);
    }
    flash_stage_kv(sb + FKV, Kh, Kl, Vh, Vl, t);
    CP_COMMIT();

    const int wm = wid * 32;
    const uint32_t aoff = (uint32_t)(wm + (lane & 15)) * LDB + ((uint32_t)(lane >> 4) << 4);
    const uint32_t koff = (uint32_t)((lane & 7) + ((lane >> 4) << 3)) * LDB
                        + ((uint32_t)((lane >> 3) & 1) << 4);
    const uint32_t voff = (uint32_t)((lane & 7) + (((lane >> 3) & 1) << 3)) * LDB
                        + ((uint32_t)(lane >> 4) << 4);
    const uint32_t aQH = sb + FQ_H + aoff, aQL = sb + FQ_L + aoff;

    float mr[2][2], lr[2][2];
    #pragma unroll
    for (int m = 0; m < 2; m++) { mr[m][0] = mr[m][1] = -INFINITY; lr[m][0] = lr[m][1] = 0.f; }
    float oc[2][8][4];
    #pragma unroll
    for (int m = 0; m < 2; m++)
        #pragma unroll
        for (int b = 0; b < 8; b++)
            #pragma unroll
            for (int k = 0; k < 4; k++) oc[m][b][k] = 0.f;

    #pragma unroll 1
    for (int tile = 0; tile < SEQ / BKV; tile++) {
        if (tile < SEQ / BKV - 1) {
            const size_t kv1 = (size_t)(tile + 1) * BKV * HD;
            flash_stage_kv(sb + FKV + ((tile + 1) & 1) * F_STG,
                           Kh + kv1, Kl + kv1, Vh + kv1, Vl + kv1, t);
        }
        CP_COMMIT();
        CP_WAIT1();
        __syncthreads();

        const uint32_t st = sb + FKV + (tile & 1) * F_STG;
        const uint32_t bKH = st + koff,          bKL = st + 9216u + koff;
        const uint32_t bVH = st + 18432u + voff, bVL = st + 27648u + voff;

        // ---- S = Q K^T ----
        float sc[2][8][4];
        #pragma unroll
        for (int m = 0; m < 2; m++)
            #pragma unroll
            for (int b = 0; b < 8; b++)
                #pragma unroll
                for (int k = 0; k < 4; k++) sc[m][b][k] = 0.f;

        #pragma unroll
        for (int kk = 0; kk < 4; kk++) {
            uint32_t aH[2][4], aL[2][4];
            ldsm4(aH[0], aQH + kk * 32u);
            ldsm4(aL[0], aQL + kk * 32u);
            ldsm4(aH[1], aQH + 16u * LDB + kk * 32u);
            ldsm4(aL[1], aQL + 16u * LDB + kk * 32u);
            #pragma unroll
            for (int j = 0; j < 4; j++) {
                uint32_t bH[4], bL[4];
                ldsm4(bH, bKH + (uint32_t)j * (16u * LDB) + kk * 32u);
                ldsm4(bL, bKL + (uint32_t)j * (16u * LDB) + kk * 32u);
                #pragma unroll
                for (int m = 0; m < 2; m++) {
                    mma16816(sc[m][2*j],   aH[m], bH[0], bH[1]);
                    mma16816(sc[m][2*j+1], aH[m], bH[2], bH[3]);
                    mma16816(sc[m][2*j],   aH[m], bL[0], bL[1]);
                    mma16816(sc[m][2*j+1], aH[m], bL[2], bL[3]);
                    mma16816(sc[m][2*j],   aL[m], bH[0], bH[1]);
                    mma16816(sc[m][2*j+1], aL[m], bH[2], bH[3]);
                }
            }
        }

        // ---- online softmax (base-2) + P fragments ----
        uint32_t pH[2][4][4], pL[2][4][4];
        #pragma unroll
        for (int m = 0; m < 2; m++) {
            float mx0 = -INFINITY, mx1 = -INFINITY;
            #pragma unroll
            for (int b = 0; b < 8; b++) {
                mx0 = fmaxf(mx0, fmaxf(sc[m][b][0], sc[m][b][1]));
                mx1 = fmaxf(mx1, fmaxf(sc[m][b][2], sc[m][b][3]));
            }
            mx0 = fmaxf(mx0, __shfl_xor_sync(0xffffffffu, mx0, 1));
            mx0 = fmaxf(mx0, __shfl_xor_sync(0xffffffffu, mx0, 2));
            mx1 = fmaxf(mx1, __shfl_xor_sync(0xffffffffu, mx1, 1));
            mx1 = fmaxf(mx1, __shfl_xor_sync(0xffffffffu, mx1, 2));
            const float mn0 = fmaxf(mr[m][0], mx0);
            const float mn1 = fmaxf(mr[m][1], mx1);
            const float al0 = ex2f(mr[m][0] - mn0);
            const float al1 = ex2f(mr[m][1] - mn1);
            mr[m][0] = mn0; mr[m][1] = mn1;

            float s0 = 0.f, s1 = 0.f;
            #pragma unroll
            for (int kk = 0; kk < 4; kk++) {
                float p00 = ex2f(sc[m][2*kk][0]   - mn0), p01 = ex2f(sc[m][2*kk][1]   - mn0);
                float p02 = ex2f(sc[m][2*kk][2]   - mn1), p03 = ex2f(sc[m][2*kk][3]   - mn1);
                float q00 = ex2f(sc[m][2*kk+1][0] - mn0), q01 = ex2f(sc[m][2*kk+1][1] - mn0);
                float q02 = ex2f(sc[m][2*kk+1][2] - mn1), q03 = ex2f(sc[m][2*kk+1][3] - mn1);
                s0 += p00 + p01 + q00 + q01;
                s1 += p02 + p03 + q02 + q03;
                pH[m][kk][0] = bf2(p00, p01);  pL[m][kk][0] = lo_res(pH[m][kk][0], p00, p01);
                pH[m][kk][1] = bf2(p02, p03);  pL[m][kk][1] = lo_res(pH[m][kk][1], p02, p03);
                pH[m][kk][2] = bf2(q00, q01);  pL[m][kk][2] = lo_res(pH[m][kk][2], q00, q01);
                pH[m][kk][3] = bf2(q02, q03);  pL[m][kk][3] = lo_res(pH[m][kk][3], q02, q03);
            }
            s0 += __shfl_xor_sync(0xffffffffu, s0, 1);
            s0 += __shfl_xor_sync(0xffffffffu, s0, 2);
            s1 += __shfl_xor_sync(0xffffffffu, s1, 1);
            s1 += __shfl_xor_sync(0xffffffffu, s1, 2);
            lr[m][0] = lr[m][0] * al0 + s0;
            lr[m][1] = lr[m][1] * al1 + s1;
            #pragma unroll
            for (int b = 0; b < 8; b++) {
                oc[m][b][0] *= al0; oc[m][b][1] *= al0;
                oc[m][b][2] *= al1; oc[m][b][3] *= al1;
            }
        }

        // ---- O += P V (V via ldmatrix.trans) ----
        #pragma unroll
        for (int kk = 0; kk < 4; kk++) {
            #pragma unroll
            for (int j = 0; j < 4; j++) {
                uint32_t vH[4], vL[4];
                ldsm4t(vH, bVH + (uint32_t)kk * (16u * LDB) + (uint32_t)j * 32u);
                ldsm4t(vL, bVL + (uint32_t)kk * (16u * LDB) + (uint32_t)j * 32u);
                #pragma unroll
                for (int m = 0; m < 2; m++) {
                    mma16816(oc[m][2*j],   pH[m][kk], vH[0], vH[1]);
                    mma16816(oc[m][2*j+1], pH[m][kk], vH[2], vH[3]);
                    mma16816(oc[m][2*j],   pH[m][kk], vL[0], vL[1]);
                    mma16816(oc[m][2*j+1], pH[m][kk], vL[2], vL[3]);
                    mma16816(oc[m][2*j],   pL[m][kk], vH[0], vH[1]);
                    mma16816(oc[m][2*j+1], pL[m][kk], vH[2], vH[3]);
                }
            }
        }
        __syncthreads();
    }

    // ---- finalize: O /= l, split hi/lo, store planes ----
    const int g  = lane >> 2;
    const int tg = lane & 3;
    #pragma unroll
    for (int m = 0; m < 2; m++) {
        const float inv0 = 1.f / lr[m][0];
        const float inv1 = 1.f / lr[m][1];
        #pragma unroll
        for (int b = 0; b < 8; b++) {
            const int d = b * 8 + tg * 2;
            {
                const size_t off = base + (size_t)(q0 + wm + m * 16 + g) * HD + d;
                float v0 = oc[m][b][0] * inv0, v1 = oc[m][b][1] * inv0;
                uint32_t h0 = bf2(v0, v1);
                *(uint32_t*)(g_Oh + off) = h0;
                *(uint32_t*)(g_Ol + off) = lo_res(h0, v0, v1);
            }
            {
                const size_t off = base + (size_t)(q0 + wm + m * 16 + g + 8) * HD + d;
                float v0 = oc[m][b][2] * inv1, v1 = oc[m][b][3] * inv1;
                uint32_t h0 = bf2(v0, v1);
                *(uint32_t*)(g_Oh + off) = h0;
                *(uint32_t*)(g_Ol + off) = lo_res(h0, v0, v1);
            }
        }
    }
}

// ---------------------------------------------------------------------------
// Kernel 3: out = O @ Wo^T + bo + x, bf16 planes + cp.async pipeline.
// grid = (64, 4).
// ---------------------------------------------------------------------------
static __device__ __forceinline__ void oproj_stage(
    uint32_t sdst, int bm0, int bn0, int c, int t)
{
    const __nv_bfloat16* WH = g_Wh + (size_t)3 * EMB * EMB + (size_t)bn0 * EMB + c * 64;
    const __nv_bfloat16* WL = g_Wl + (size_t)3 * EMB * EMB + (size_t)bn0 * EMB + c * 64;
    #pragma unroll
    for (int i = 0; i < 16; i++) {
        int j = t + 256 * i;
        int plane = j >> 10;
        int r  = (j >> 3) & 127;
        int c8 = j & 7;
        uint32_t dst = sdst + (uint32_t)plane * 18432u
                     + (uint32_t)r * LDB + (uint32_t)c8 * 16u;
        if (plane < 2) {
            const int nrow = bm0 + r;
            const int bb = nrow >> 12, s = nrow & (SEQ - 1);
            const __nv_bfloat16* src = (plane == 0) ? g_Oh : g_Ol;
            CP16(dst, src + ((size_t)(bb * NH + c) * SEQ + s) * HD + c8 * 8);
        } else {
            const __nv_bfloat16* src = (plane == 2) ? WH : WL;
            CP16(dst, src + (size_t)r * EMB + c8 * 8);
        }
    }
}

__global__ void __launch_bounds__(256, 1) out_proj_mma(
    const float* __restrict__ x,
    const float* __restrict__ bo,
    float* __restrict__ out)
{
    extern __shared__ char smem[];
    const uint32_t sb = smem_u32(smem);

    const int t    = threadIdx.x;
    const int wid  = t >> 5;
    const int lane = t & 31;
    const int bm0  = blockIdx.x * 128;
    const int bn0  = blockIdx.y * 128;
    const int wm   = (wid & 3) * 32;
    const int wn   = (wid >> 2) * 64;

    const uint32_t aoff = (uint32_t)(wm + (lane & 15)) * LDB + ((uint32_t)(lane >> 4) << 4);
    const uint32_t boff = (uint32_t)(wn + (lane & 7) + ((lane >> 4) << 3)) * LDB
                        + ((uint32_t)((lane >> 3) & 1) << 4);

    float acc[2][8][4];
    #pragma unroll
    for (int m = 0; m < 2; m++)
        #pragma unroll
        for (int b = 0; b < 8; b++)
            #pragma unroll
            for (int k = 0; k < 4; k++) acc[m][b][k] = 0.f;

    oproj_stage(sb, bm0, bn0, 0, t);
    CP_COMMIT();

    #pragma unroll 1
    for (int c = 0; c < 8; c++) {
        if (c < 7) oproj_stage(sb + ((c + 1) & 1) * P_STG, bm0, bn0, c + 1, t);
        CP_COMMIT();
        CP_WAIT1();
        __syncthreads();

        const uint32_t st = sb + (c & 1) * P_STG;
        const uint32_t aAH = st + P_AH + aoff, aAL = st + P_AL + aoff;
        const uint32_t bBH = st + P_BH + boff, bBL = st + P_BL + boff;

        #pragma unroll
        for (int kk = 0; kk < 4; kk++) {
            uint32_t aH[2][4], aL[2][4];
            ldsm4(aH[0], aAH + kk * 32u);
            ldsm4(aL[0], aAL + kk * 32u);
            ldsm4(aH[1], aAH + 16u * LDB + kk * 32u);
            ldsm4(aL[1], aAL + 16u * LDB + kk * 32u);
            #pragma unroll
            for (int j = 0; j < 4; j++) {
                uint32_t bH[4], bL[4];
                ldsm4(bH, bBH + (uint32_t)j * (16u * LDB) + kk * 32u);
                ldsm4(bL, bBL + (uint32_t)j * (16u * LDB) + kk * 32u);
                #pragma unroll
                for (int m = 0; m < 2; m++) {
                    mma16816(acc[m][2*j],   aH[m], bH[0], bH[1]);
                    mma16816(acc[m][2*j+1], aH[m], bH[2], bH[3]);
                    mma16816(acc[m][2*j],   aH[m], bL[0], bL[1]);
                    mma16816(acc[m][2*j+1], aH[m], bL[2], bL[3]);
                    mma16816(acc[m][2*j],   aL[m], bH[0], bH[1]);
                    mma16816(acc[m][2*j+1], aL[m], bH[2], bH[3]);
                }
            }
        }
        __syncthreads();
    }

    // epilogue: + bo + residual x
    const int g  = lane >> 2;
    const int tg = lane & 3;
    #pragma unroll
    for (int m = 0; m < 2; m++) {
        #pragma unroll
        for (int b = 0; b < 8; b++) {
            const int col = bn0 + wn + b * 8 + tg * 2;
            const float b0v = bo[col], b1v = bo[col + 1];
            #pragma unroll
            for (int rr = 0; rr < 2; rr++) {
                const int row = bm0 + wm + m * 16 + g + rr * 8;
                float2 xr = *(const float2*)(x + (size_t)row * EMB + col);
                float2 v = make_float2(acc[m][b][2*rr]   + b0v + xr.x,
                                       acc[m][b][2*rr+1] + b1v + xr.y);
                *(float2*)(out + (size_t)row * EMB + col) = v;
            }
        }
    }
}

// ---------------------------------------------------------------------------
extern "C" void kernel_launch(void* const* d_in, const int* in_sizes, int n_in,
                              void* d_out, int out_size)
{
    const float* x  = (const float*)d_in[0];
    const float* Wq = (const float*)d_in[1];
    const float* bq = (const float*)d_in[2];
    const float* Wk = (const float*)d_in[3];
    const float* bk = (const float*)d_in[4];
    const float* Wv = (const float*)d_in[5];
    const float* bv = (const float*)d_in[6];
    const float* Wo = (const float*)d_in[7];
    const float* bo = (const float*)d_in[8];
    float* out = (float*)d_out;

    cudaFuncSetAttribute(proj_qkv_mma,
                         cudaFuncAttributeMaxDynamicSharedMemorySize, SMEM_PROJ);
    cudaFuncSetAttribute(out_proj_mma,
                         cudaFuncAttributeMaxDynamicSharedMemorySize, SMEM_PROJ);
    cudaFuncSetAttribute(flash_mma,
                         cudaFuncAttributeMaxDynamicSharedMemorySize, SMEM_FLASH);

    const int NCONV = (NROWS * EMB / 4 + 4 * EMB * EMB / 4 + 255) / 256;
    convert_inputs<<<NCONV, 256>>>(x, Wq, Wk, Wv, Wo);
    proj_qkv_mma<<<dim3(NROWS/128, EMB/128, 3), 256, SMEM_PROJ>>>(bq, bk, bv);
    flash_mma<<<dim3(SEQ/BQ, NB*NH), 256, SMEM_FLASH>>>();
    out_proj_mma<<<dim3(NROWS/128, EMB/128), 256, SMEM_PROJ>>>(x, bo, out);
}

// round 8
// speedup vs baseline: 4.6391x; 1.3870x over previous
#include <cuda_runtime.h>
#include <cuda_fp16.h>
#include <math.h>
#include <stdint.h>

#define NB   2
#define SEQ  4096
#define EMB  512
#define NH   8
#define HD   64
#define NROWS (NB*SEQ)   // 8192

// fp16 plane scratch (allocation-free). A-operands split hi/lo; B-operands single.
__device__ __half g_xh[NROWS*EMB], g_xl[NROWS*EMB];
__device__ __half g_Wh[4*EMB*EMB];                       // single plane
__device__ __half g_Qh[NB*NH*SEQ*HD], g_Ql[NB*NH*SEQ*HD];
__device__ __half g_Kh[NB*NH*SEQ*HD];                    // single
__device__ __half g_Vh[NB*NH*SEQ*HD];                    // single
__device__ __half g_Oh[NB*NH*SEQ*HD], g_Ol[NB*NH*SEQ*HD];

// ============================ helpers ============================
static __device__ __forceinline__ uint32_t smem_u32(const void* p) {
    uint32_t a;
    asm("{ .reg .u64 t; cvta.to.shared.u64 t, %1; cvt.u32.u64 %0, t; }"
        : "=r"(a) : "l"(p));
    return a;
}
static __device__ __forceinline__ float ex2f(float x) {
    float r;
    asm("ex2.approx.f32 %0, %1;" : "=f"(r) : "f"(x));
    return r;
}
static __device__ __forceinline__ uint32_t f2h2(float a, float b) {
    __half2 t = __floats2half2_rn(a, b);
    return *reinterpret_cast<uint32_t*>(&t);
}
static __device__ __forceinline__ uint32_t h2_res(uint32_t h, float a, float b) {
    __half2 t = *reinterpret_cast<__half2*>(&h);
    return f2h2(a - __half2float(t.x), b - __half2float(t.y));
}
static __device__ __forceinline__ void ldsm4(uint32_t r[4], uint32_t addr) {
    asm volatile("ldmatrix.sync.aligned.m8n8.x4.shared.b16 {%0,%1,%2,%3}, [%4];"
                 : "=r"(r[0]), "=r"(r[1]), "=r"(r[2]), "=r"(r[3]) : "r"(addr));
}
static __device__ __forceinline__ void ldsm4t(uint32_t r[4], uint32_t addr) {
    asm volatile("ldmatrix.sync.aligned.m8n8.x4.trans.shared.b16 {%0,%1,%2,%3}, [%4];"
                 : "=r"(r[0]), "=r"(r[1]), "=r"(r[2]), "=r"(r[3]) : "r"(addr));
}
static __device__ __forceinline__ void mma16816(float c[4], const uint32_t a[4],
                                                uint32_t b0, uint32_t b1) {
    asm volatile(
        "mma.sync.aligned.m16n8k16.row.col.f32.f16.f16.f32 "
        "{%0,%1,%2,%3}, {%4,%5,%6,%7}, {%8,%9}, {%0,%1,%2,%3};"
        : "+f"(c[0]), "+f"(c[1]), "+f"(c[2]), "+f"(c[3])
        : "r"(a[0]), "r"(a[1]), "r"(a[2]), "r"(a[3]), "r"(b0), "r"(b1));
}
#define CP16(dst, src) asm volatile("cp.async.cg.shared.global [%0], [%1], 16;" :: "r"(dst), "l"(src))
#define CP_COMMIT()    asm volatile("cp.async.commit_group;")
#define CP_WAIT1()     asm volatile("cp.async.wait_group 1;")

#define LDB  144           // 64+8 fp16 elems per row, bytes

// ---------------------------------------------------------------------------
// Kernel 0: split x into fp16 hi/lo planes; weights into single fp16 plane.
// ---------------------------------------------------------------------------
__global__ void __launch_bounds__(256) convert_inputs(
    const float* __restrict__ x,
    const float* __restrict__ Wq, const float* __restrict__ Wk,
    const float* __restrict__ Wv, const float* __restrict__ Wo)
{
    const int NX4 = NROWS * EMB / 4;      // 1048576
    const int NW4 = EMB * EMB / 4;        // 65536
    int i4 = blockIdx.x * 256 + threadIdx.x;
    if (i4 < NX4) {
        float4 v = ((const float4*)x)[i4];
        uint32_t h0 = f2h2(v.x, v.y), h1 = f2h2(v.z, v.w);
        ((uint2*)g_xh)[i4] = make_uint2(h0, h1);
        ((uint2*)g_xl)[i4] = make_uint2(h2_res(h0, v.x, v.y), h2_res(h1, v.z, v.w));
    } else {
        int r = i4 - NX4;
        int w = r / NW4;
        if (w >= 4) return;
        int j = r - w * NW4;
        const float* W = (w == 0) ? Wq : (w == 1) ? Wk : (w == 2) ? Wv : Wo;
        float4 v = ((const float4*)W)[j];
        ((uint2*)(g_Wh + (size_t)w * EMB * EMB))[j] =
            make_uint2(f2h2(v.x, v.y), f2h2(v.z, v.w));
    }
}

// ============================ proj smem ============================
// per stage: A_H 0, A_L 18432, B 36864 ; stage size 55296
#define P_AH 0
#define P_AL 18432
#define P_B  36864
#define P_STG 55296
#define SMEM_PROJ (2*P_STG)   // 110592

// stage one k-chunk (A hi/lo + B single) via cp.async: 3072 x 16B
static __device__ __forceinline__ void proj_stage(
    uint32_t sdst, const __half* Ah, const __half* Al, const __half* B, int t)
{
    #pragma unroll
    for (int i = 0; i < 12; i++) {
        int j = t + 256 * i;          // 0..3071
        int plane = j >> 10;          // 0..2
        int r  = (j >> 3) & 127;
        int c8 = j & 7;
        const __half* src = (plane == 0) ? Ah : (plane == 1) ? Al : B;
        uint32_t dst = sdst + (uint32_t)plane * 18432u
                     + (uint32_t)r * LDB + (uint32_t)c8 * 16u;
        CP16(dst, src + (size_t)r * EMB + c8 * 8);
    }
}

// ---------------------------------------------------------------------------
// Kernel 1: QKV projection, fp16 2-term. CTA 128x128, warp 32x64. grid=(64,4,3).
// Q written as hi/lo planes (pre-scaled); K/V single plane.
// ---------------------------------------------------------------------------
__global__ void __launch_bounds__(256, 1) proj_qkv_mma(
    const float* __restrict__ bq, const float* __restrict__ bk,
    const float* __restrict__ bv)
{
    extern __shared__ char smem[];
    const uint32_t sb = smem_u32(smem);

    const int z = blockIdx.z;
    const float* bias = (z == 0) ? bq : (z == 1) ? bk : bv;
    const __half* WH = g_Wh + (size_t)z * EMB * EMB;

    const int t    = threadIdx.x;
    const int wid  = t >> 5;
    const int lane = t & 31;
    const int bm0  = blockIdx.x * 128;
    const int bn0  = blockIdx.y * 128;
    const int wm   = (wid & 3) * 32;
    const int wn   = (wid >> 2) * 64;

    const uint32_t aoff = (uint32_t)(wm + (lane & 15)) * LDB + ((uint32_t)(lane >> 4) << 4);
    const uint32_t boff = (uint32_t)(wn + (lane & 7) + ((lane >> 4) << 3)) * LDB
                        + ((uint32_t)((lane >> 3) & 1) << 4);

    float acc[2][8][4];
    #pragma unroll
    for (int m = 0; m < 2; m++)
        #pragma unroll
        for (int b = 0; b < 8; b++)
            #pragma unroll
            for (int k = 0; k < 4; k++) acc[m][b][k] = 0.f;

    proj_stage(sb, g_xh + (size_t)bm0 * EMB, g_xl + (size_t)bm0 * EMB,
               WH + (size_t)bn0 * EMB, t);
    CP_COMMIT();

    #pragma unroll 1
    for (int c = 0; c < 8; c++) {
        if (c < 7) {
            const int k1 = (c + 1) * 64;
            proj_stage(sb + ((c + 1) & 1) * P_STG,
                       g_xh + (size_t)bm0 * EMB + k1, g_xl + (size_t)bm0 * EMB + k1,
                       WH + (size_t)bn0 * EMB + k1, t);
        }
        CP_COMMIT();
        CP_WAIT1();
        __syncthreads();

        const uint32_t st = sb + (c & 1) * P_STG;
        const uint32_t aAH = st + P_AH + aoff, aAL = st + P_AL + aoff;
        const uint32_t bBB = st + P_B + boff;

        #pragma unroll
        for (int kk = 0; kk < 4; kk++) {
            uint32_t aH[2][4], aL[2][4];
            ldsm4(aH[0], aAH + kk * 32u);
            ldsm4(aL[0], aAL + kk * 32u);
            ldsm4(aH[1], aAH + 16u * LDB + kk * 32u);
            ldsm4(aL[1], aAL + 16u * LDB + kk * 32u);
            #pragma unroll
            for (int j = 0; j < 4; j++) {
                uint32_t bb[4];
                ldsm4(bb, bBB + (uint32_t)j * (16u * LDB) + kk * 32u);
                #pragma unroll
                for (int m = 0; m < 2; m++) {
                    mma16816(acc[m][2*j],   aH[m], bb[0], bb[1]);
                    mma16816(acc[m][2*j+1], aH[m], bb[2], bb[3]);
                    mma16816(acc[m][2*j],   aL[m], bb[0], bb[1]);
                    mma16816(acc[m][2*j+1], aL[m], bb[2], bb[3]);
                }
            }
        }
        __syncthreads();
    }

    // epilogue: +bias, scatter. Q: pre-scale + hi/lo split; K/V: single plane.
    const float qscale = (z == 0) ? 0.125f * 1.4426950408889634f : 1.0f;
    const int g  = lane >> 2;
    const int tg = lane & 3;
    #pragma unroll
    for (int m = 0; m < 2; m++) {
        #pragma unroll
        for (int b = 0; b < 8; b++) {
            const int col = bn0 + wn + b * 8 + tg * 2;
            const int h = col >> 6, d = col & 63;
            const float b0v = bias[col], b1v = bias[col + 1];
            #pragma unroll
            for (int rr = 0; rr < 2; rr++) {
                const int row = bm0 + wm + m * 16 + g + rr * 8;
                const int bb = row >> 12, s = row & (SEQ - 1);
                float v0 = (acc[m][b][2*rr]   + b0v) * qscale;
                float v1 = (acc[m][b][2*rr+1] + b1v) * qscale;
                size_t off = ((size_t)(bb * NH + h) * SEQ + s) * HD + d;
                uint32_t h0 = f2h2(v0, v1);
                if (z == 0) {
                    *(uint32_t*)(g_Qh + off) = h0;
                    *(uint32_t*)(g_Ql + off) = h2_res(h0, v0, v1);
                } else if (z == 1) {
                    *(uint32_t*)(g_Kh + off) = h0;
                } else {
                    *(uint32_t*)(g_Vh + off) = h0;
                }
            }
        }
    }
}

// ============================ flash smem ============================
#define BQ   256
#define BKV  64
#define FQ_H 0
#define FQ_L (FQ_H + BQ*LDB)     // 36864
#define FKV  (FQ_L + BQ*LDB)     // 73728
// per stage: K 0, V 9216 ; stage size 18432
#define F_STG 18432
#define SMEM_FLASH (FKV + 2*F_STG)  // 110592

static __device__ __forceinline__ void flash_stage_kv(
    uint32_t sdst, const __half* Kh, const __half* Vh, int t)
{
    #pragma unroll
    for (int i = 0; i < 4; i++) {
        int j = t + 256 * i;          // 0..1023
        int plane = j >> 9;           // 0..1
        int r  = (j >> 3) & 63;
        int c8 = j & 7;
        const __half* src = plane ? Vh : Kh;
        uint32_t dst = sdst + (uint32_t)plane * 9216u
                     + (uint32_t)r * LDB + (uint32_t)c8 * 16u;
        CP16(dst, src + (size_t)r * HD + c8 * 8);
    }
}

// ---------------------------------------------------------------------------
// Kernel 2: flash attention, fp16 2-term. BQ=256 (8 warps x 32 rows),
// BKV=64, cp.async double-buffered KV. grid = (SEQ/256, NB*NH).
// ---------------------------------------------------------------------------
__global__ void __launch_bounds__(256, 1) flash_mma()
{
    extern __shared__ char smem[];
    const uint32_t sb = smem_u32(smem);

    const int t    = threadIdx.x;
    const int wid  = t >> 5;
    const int lane = t & 31;
    const int bh   = blockIdx.y;
    const int q0   = blockIdx.x * BQ;

    const size_t base = (size_t)bh * SEQ * HD;
    const __half* Qh = g_Qh + base;
    const __half* Ql = g_Ql + base;
    const __half* Kh = g_Kh + base;
    const __half* Vh = g_Vh + base;

    // ---- stage Q (hi/lo) + first KV tile ----
    #pragma unroll
    for (int i = 0; i < 16; i++) {
        int j = t + 256 * i;          // 0..4095
        int plane = j >> 11;          // 0..1
        int r  = (j >> 3) & 255;
        int c8 = j & 7;
        const __half* src = plane ? Ql : Qh;
        uint32_t dst = sb + (plane ? FQ_L : FQ_H)
                     + (uint32_t)r * LDB + (uint32_t)c8 * 16u;
        CP16(dst, src + (size_t)(q0 + r) * HD + c8 * 8);
    }
    flash_stage_kv(sb + FKV, Kh, Vh, t);
    CP_COMMIT();

    const int wm = wid * 32;
    const uint32_t aoff = (uint32_t)(wm + (lane & 15)) * LDB + ((uint32_t)(lane >> 4) << 4);
    const uint32_t koff = (uint32_t)((lane & 7) + ((lane >> 4) << 3)) * LDB
                        + ((uint32_t)((lane >> 3) & 1) << 4);
    const uint32_t voff = (uint32_t)((lane & 7) + (((lane >> 3) & 1) << 3)) * LDB
                        + ((uint32_t)(lane >> 4) << 4);
    const uint32_t aQH = sb + FQ_H + aoff, aQL = sb + FQ_L + aoff;

    float mr[2][2], lr[2][2];
    #pragma unroll
    for (int m = 0; m < 2; m++) { mr[m][0] = mr[m][1] = -INFINITY; lr[m][0] = lr[m][1] = 0.f; }
    float oc[2][8][4];
    #pragma unroll
    for (int m = 0; m < 2; m++)
        #pragma unroll
        for (int b = 0; b < 8; b++)
            #pragma unroll
            for (int k = 0; k < 4; k++) oc[m][b][k] = 0.f;

    #pragma unroll 1
    for (int tile = 0; tile < SEQ / BKV; tile++) {
        if (tile < SEQ / BKV - 1) {
            const size_t kv1 = (size_t)(tile + 1) * BKV * HD;
            flash_stage_kv(sb + FKV + ((tile + 1) & 1) * F_STG, Kh + kv1, Vh + kv1, t);
        }
        CP_COMMIT();
        CP_WAIT1();
        __syncthreads();

        const uint32_t st = sb + FKV + (tile & 1) * F_STG;
        const uint32_t bKK = st + koff;
        const uint32_t bVV = st + 9216u + voff;

        // ---- S = Q K^T (Q split, K single) ----
        float sc[2][8][4];
        #pragma unroll
        for (int m = 0; m < 2; m++)
            #pragma unroll
            for (int b = 0; b < 8; b++)
                #pragma unroll
                for (int k = 0; k < 4; k++) sc[m][b][k] = 0.f;

        #pragma unroll
        for (int kk = 0; kk < 4; kk++) {
            uint32_t aH[2][4], aL[2][4];
            ldsm4(aH[0], aQH + kk * 32u);
            ldsm4(aL[0], aQL + kk * 32u);
            ldsm4(aH[1], aQH + 16u * LDB + kk * 32u);
            ldsm4(aL[1], aQL + 16u * LDB + kk * 32u);
            #pragma unroll
            for (int j = 0; j < 4; j++) {
                uint32_t bb[4];
                ldsm4(bb, bKK + (uint32_t)j * (16u * LDB) + kk * 32u);
                #pragma unroll
                for (int m = 0; m < 2; m++) {
                    mma16816(sc[m][2*j],   aH[m], bb[0], bb[1]);
                    mma16816(sc[m][2*j+1], aH[m], bb[2], bb[3]);
                    mma16816(sc[m][2*j],   aL[m], bb[0], bb[1]);
                    mma16816(sc[m][2*j+1], aL[m], bb[2], bb[3]);
                }
            }
        }

        // ---- online softmax (base-2) + P fragments (fp16 hi/lo) ----
        uint32_t pH[2][4][4], pL[2][4][4];
        #pragma unroll
        for (int m = 0; m < 2; m++) {
            float mx0 = -INFINITY, mx1 = -INFINITY;
            #pragma unroll
            for (int b = 0; b < 8; b++) {
                mx0 = fmaxf(mx0, fmaxf(sc[m][b][0], sc[m][b][1]));
                mx1 = fmaxf(mx1, fmaxf(sc[m][b][2], sc[m][b][3]));
            }
            mx0 = fmaxf(mx0, __shfl_xor_sync(0xffffffffu, mx0, 1));
            mx0 = fmaxf(mx0, __shfl_xor_sync(0xffffffffu, mx0, 2));
            mx1 = fmaxf(mx1, __shfl_xor_sync(0xffffffffu, mx1, 1));
            mx1 = fmaxf(mx1, __shfl_xor_sync(0xffffffffu, mx1, 2));
            const float mn0 = fmaxf(mr[m][0], mx0);
            const float mn1 = fmaxf(mr[m][1], mx1);
            const float al0 = ex2f(mr[m][0] - mn0);
            const float al1 = ex2f(mr[m][1] - mn1);
            mr[m][0] = mn0; mr[m][1] = mn1;

            float s0 = 0.f, s1 = 0.f;
            #pragma unroll
            for (int kk = 0; kk < 4; kk++) {
                float p00 = ex2f(sc[m][2*kk][0]   - mn0), p01 = ex2f(sc[m][2*kk][1]   - mn0);
                float p02 = ex2f(sc[m][2*kk][2]   - mn1), p03 = ex2f(sc[m][2*kk][3]   - mn1);
                float q00 = ex2f(sc[m][2*kk+1][0] - mn0), q01 = ex2f(sc[m][2*kk+1][1] - mn0);
                float q02 = ex2f(sc[m][2*kk+1][2] - mn1), q03 = ex2f(sc[m][2*kk+1][3] - mn1);
                s0 += p00 + p01 + q00 + q01;
                s1 += p02 + p03 + q02 + q03;
                pH[m][kk][0] = f2h2(p00, p01);  pL[m][kk][0] = h2_res(pH[m][kk][0], p00, p01);
                pH[m][kk][1] = f2h2(p02, p03);  pL[m][kk][1] = h2_res(pH[m][kk][1], p02, p03);
                pH[m][kk][2] = f2h2(q00, q01);  pL[m][kk][2] = h2_res(pH[m][kk][2], q00, q01);
                pH[m][kk][3] = f2h2(q02, q03);  pL[m][kk][3] = h2_res(pH[m][kk][3], q02, q03);
            }
            s0 += __shfl_xor_sync(0xffffffffu, s0, 1);
            s0 += __shfl_xor_sync(0xffffffffu, s0, 2);
            s1 += __shfl_xor_sync(0xffffffffu, s1, 1);
            s1 += __shfl_xor_sync(0xffffffffu, s1, 2);
            lr[m][0] = lr[m][0] * al0 + s0;
            lr[m][1] = lr[m][1] * al1 + s1;
            #pragma unroll
            for (int b = 0; b < 8; b++) {
                oc[m][b][0] *= al0; oc[m][b][1] *= al0;
                oc[m][b][2] *= al1; oc[m][b][3] *= al1;
            }
        }

        // ---- O += P V (P split, V single via ldmatrix.trans) ----
        #pragma unroll
        for (int kk = 0; kk < 4; kk++) {
            #pragma unroll
            for (int j = 0; j < 4; j++) {
                uint32_t vv[4];
                ldsm4t(vv, bVV + (uint32_t)kk * (16u * LDB) + (uint32_t)j * 32u);
                #pragma unroll
                for (int m = 0; m < 2; m++) {
                    mma16816(oc[m][2*j],   pH[m][kk], vv[0], vv[1]);
                    mma16816(oc[m][2*j+1], pH[m][kk], vv[2], vv[3]);
                    mma16816(oc[m][2*j],   pL[m][kk], vv[0], vv[1]);
                    mma16816(oc[m][2*j+1], pL[m][kk], vv[2], vv[3]);
                }
            }
        }
        __syncthreads();
    }

    // ---- finalize: O /= l, split hi/lo fp16 planes ----
    const int g  = lane >> 2;
    const int tg = lane & 3;
    #pragma unroll
    for (int m = 0; m < 2; m++) {
        const float inv0 = 1.f / lr[m][0];
        const float inv1 = 1.f / lr[m][1];
        #pragma unroll
        for (int b = 0; b < 8; b++) {
            const int d = b * 8 + tg * 2;
            {
                const size_t off = base + (size_t)(q0 + wm + m * 16 + g) * HD + d;
                float v0 = oc[m][b][0] * inv0, v1 = oc[m][b][1] * inv0;
                uint32_t h0 = f2h2(v0, v1);
                *(uint32_t*)(g_Oh + off) = h0;
                *(uint32_t*)(g_Ol + off) = h2_res(h0, v0, v1);
            }
            {
                const size_t off = base + (size_t)(q0 + wm + m * 16 + g + 8) * HD + d;
                float v0 = oc[m][b][2] * inv1, v1 = oc[m][b][3] * inv1;
                uint32_t h0 = f2h2(v0, v1);
                *(uint32_t*)(g_Oh + off) = h0;
                *(uint32_t*)(g_Ol + off) = h2_res(h0, v0, v1);
            }
        }
    }
}

// ---------------------------------------------------------------------------
// Kernel 3: out = O @ Wo^T + bo + x, fp16 2-term. grid = (64, 4).
// ---------------------------------------------------------------------------
static __device__ __forceinline__ void oproj_stage(
    uint32_t sdst, int bm0, int bn0, int c, int t)
{
    const __half* WH = g_Wh + (size_t)3 * EMB * EMB + (size_t)bn0 * EMB + c * 64;
    #pragma unroll
    for (int i = 0; i < 12; i++) {
        int j = t + 256 * i;
        int plane = j >> 10;          // 0..2
        int r  = (j >> 3) & 127;
        int c8 = j & 7;
        uint32_t dst = sdst + (uint32_t)plane * 18432u
                     + (uint32_t)r * LDB + (uint32_t)c8 * 16u;
        if (plane < 2) {
            const int nrow = bm0 + r;
            const int bb = nrow >> 12, s = nrow & (SEQ - 1);
            const __half* src = (plane == 0) ? g_Oh : g_Ol;
            CP16(dst, src + ((size_t)(bb * NH + c) * SEQ + s) * HD + c8 * 8);
        } else {
            CP16(dst, WH + (size_t)r * EMB + c8 * 8);
        }
    }
}

__global__ void __launch_bounds__(256, 1) out_proj_mma(
    const float* __restrict__ x,
    const float* __restrict__ bo,
    float* __restrict__ out)
{
    extern __shared__ char smem[];
    const uint32_t sb = smem_u32(smem);

    const int t    = threadIdx.x;
    const int wid  = t >> 5;
    const int lane = t & 31;
    const int bm0  = blockIdx.x * 128;
    const int bn0  = blockIdx.y * 128;
    const int wm   = (wid & 3) * 32;
    const int wn   = (wid >> 2) * 64;

    const uint32_t aoff = (uint32_t)(wm + (lane & 15)) * LDB + ((uint32_t)(lane >> 4) << 4);
    const uint32_t boff = (uint32_t)(wn + (lane & 7) + ((lane >> 4) << 3)) * LDB
                        + ((uint32_t)((lane >> 3) & 1) << 4);

    float acc[2][8][4];
    #pragma unroll
    for (int m = 0; m < 2; m++)
        #pragma unroll
        for (int b = 0; b < 8; b++)
            #pragma unroll
            for (int k = 0; k < 4; k++) acc[m][b][k] = 0.f;

    oproj_stage(sb, bm0, bn0, 0, t);
    CP_COMMIT();

    #pragma unroll 1
    for (int c = 0; c < 8; c++) {
        if (c < 7) oproj_stage(sb + ((c + 1) & 1) * P_STG, bm0, bn0, c + 1, t);
        CP_COMMIT();
        CP_WAIT1();
        __syncthreads();

        const uint32_t st = sb + (c & 1) * P_STG;
        const uint32_t aAH = st + P_AH + aoff, aAL = st + P_AL + aoff;
        const uint32_t bBB = st + P_B + boff;

        #pragma unroll
        for (int kk = 0; kk < 4; kk++) {
            uint32_t aH[2][4], aL[2][4];
            ldsm4(aH[0], aAH + kk * 32u);
            ldsm4(aL[0], aAL + kk * 32u);
            ldsm4(aH[1], aAH + 16u * LDB + kk * 32u);
            ldsm4(aL[1], aAL + 16u * LDB + kk * 32u);
            #pragma unroll
            for (int j = 0; j < 4; j++) {
                uint32_t bb[4];
                ldsm4(bb, bBB + (uint32_t)j * (16u * LDB) + kk * 32u);
                #pragma unroll
                for (int m = 0; m < 2; m++) {
                    mma16816(acc[m][2*j],   aH[m], bb[0], bb[1]);
                    mma16816(acc[m][2*j+1], aH[m], bb[2], bb[3]);
                    mma16816(acc[m][2*j],   aL[m], bb[0], bb[1]);
                    mma16816(acc[m][2*j+1], aL[m], bb[2], bb[3]);
                }
            }
        }
        __syncthreads();
    }

    // epilogue: + bo + residual x
    const int g  = lane >> 2;
    const int tg = lane & 3;
    #pragma unroll
    for (int m = 0; m < 2; m++) {
        #pragma unroll
        for (int b = 0; b < 8; b++) {
            const int col = bn0 + wn + b * 8 + tg * 2;
            const float b0v = bo[col], b1v = bo[col + 1];
            #pragma unroll
            for (int rr = 0; rr < 2; rr++) {
                const int row = bm0 + wm + m * 16 + g + rr * 8;
                float2 xr = *(const float2*)(x + (size_t)row * EMB + col);
                float2 v = make_float2(acc[m][b][2*rr]   + b0v + xr.x,
                                       acc[m][b][2*rr+1] + b1v + xr.y);
                *(float2*)(out + (size_t)row * EMB + col) = v;
            }
        }
    }
}

// ---------------------------------------------------------------------------
extern "C" void kernel_launch(void* const* d_in, const int* in_sizes, int n_in,
                              void* d_out, int out_size)
{
    const float* x  = (const float*)d_in[0];
    const float* Wq = (const float*)d_in[1];
    const float* bq = (const float*)d_in[2];
    const float* Wk = (const float*)d_in[3];
    const float* bk = (const float*)d_in[4];
    const float* Wv = (const float*)d_in[5];
    const float* bv = (const float*)d_in[6];
    const float* Wo = (const float*)d_in[7];
    const float* bo = (const float*)d_in[8];
    float* out = (float*)d_out;

    cudaFuncSetAttribute(proj_qkv_mma,
                         cudaFuncAttributeMaxDynamicSharedMemorySize, SMEM_PROJ);
    cudaFuncSetAttribute(out_proj_mma,
                         cudaFuncAttributeMaxDynamicSharedMemorySize, SMEM_PROJ);
    cudaFuncSetAttribute(flash_mma,
                         cudaFuncAttributeMaxDynamicSharedMemorySize, SMEM_FLASH);

    const int NCONV = (NROWS * EMB / 4 + 4 * EMB * EMB / 4 + 255) / 256;
    convert_inputs<<<NCONV, 256>>>(x, Wq, Wk, Wv, Wo);
    proj_qkv_mma<<<dim3(NROWS/128, EMB/128, 3), 256, SMEM_PROJ>>>(bq, bk, bv);
    flash_mma<<<dim3(SEQ/BQ, NB*NH), 256, SMEM_FLASH>>>();
    out_proj_mma<<<dim3(NROWS/128, EMB/128), 256, SMEM_PROJ>>>(x, bo, out);
}